// round 3
// baseline (speedup 1.0000x reference)
#include <cuda_runtime.h>
#include <math.h>

#define NN 50000
#define EE 800000
#define DIN 256
#define DH 128
#define DOUT 128

// ---------------- scratch (device globals; no allocation allowed) -------------
__device__ float g_h[NN * DH];             // 25.6 MB
__device__ float g_qkvs[(size_t)NN * 512]; // 102.4 MB : per node [q(128) k(128) v(128) skip(128)]
__device__ float g_W2[512 * DH];           // packed W_q/W_k/W_v/W_skip
__device__ float g_b2[512];
__device__ int   g_deg[NN];
__device__ int   g_off[NN + 1];
__device__ int   g_cur[NN];
__device__ int   g_src[EE];                // edge sources sorted by dst
__device__ int   g_is64;                   // 1 if edge_index is int64, 0 if int32

// ---------------- edge dtype detection ----------------------------------------
// int64 nonneg values < 2^31: every odd 32-bit word is 0.
// int32 random ids in [0,50000): essentially impossible for 256 odd words to all be 0.
__global__ void detect_dtype_kernel(const int* __restrict__ ei_raw)
{
    __shared__ int nz;
    if (threadIdx.x == 0) nz = 0;
    __syncthreads();
    // inspect odd words of the first 512 int32 words (well within even an int32 buffer)
    int w = ei_raw[2 * threadIdx.x + 1];
    if (w != 0) atomicAdd(&nz, 1);
    __syncthreads();
    if (threadIdx.x == 0) g_is64 = (nz == 0) ? 1 : 0;
}

// ---------------- tiled fp32 GEMM body:  C[m][n] = act(sum_k A[m][k]*B[n][k] + bias[n])
template <bool RELU>
__device__ __forceinline__ void gemm_body(const float* __restrict__ A,
                                          const float* __restrict__ B,
                                          const float* __restrict__ bias,
                                          float* __restrict__ C,
                                          int M, int K, int Nout)
{
    constexpr int BM = 128, BN = 64, BK = 16, TM = 8, TN = 4;
    __shared__ float As[BK][BM];
    __shared__ float Bs[BK][BN];

    const int tid = threadIdx.x;              // 256 threads
    const int m0 = blockIdx.x * BM;
    const int n0 = blockIdx.y * BN;
    const int ty = tid / 16;
    const int tx = tid % 16;
    const int rowBase = ty * TM;
    const int colBase = tx * TN;

    float acc[TM][TN];
#pragma unroll
    for (int i = 0; i < TM; i++)
#pragma unroll
        for (int j = 0; j < TN; j++) acc[i][j] = 0.f;

    for (int k0 = 0; k0 < K; k0 += BK) {
#pragma unroll
        for (int it = 0; it < 2; ++it) {
            int idx = tid + it * 256;          // 0..511
            int r  = idx >> 2;                 // 0..127
            int c4 = idx & 3;                  // 0..3
            int gr = m0 + r;
            float4 v;
            if (gr < M) v = *(const float4*)(A + (size_t)gr * K + k0 + c4 * 4);
            else        v = make_float4(0.f, 0.f, 0.f, 0.f);
            As[c4 * 4 + 0][r] = v.x;
            As[c4 * 4 + 1][r] = v.y;
            As[c4 * 4 + 2][r] = v.z;
            As[c4 * 4 + 3][r] = v.w;
        }
        {
            int r  = tid >> 2;                 // 0..63
            int c4 = tid & 3;
            float4 v = *(const float4*)(B + (size_t)(n0 + r) * K + k0 + c4 * 4);
            Bs[c4 * 4 + 0][r] = v.x;
            Bs[c4 * 4 + 1][r] = v.y;
            Bs[c4 * 4 + 2][r] = v.z;
            Bs[c4 * 4 + 3][r] = v.w;
        }
        __syncthreads();

#pragma unroll
        for (int kk = 0; kk < BK; ++kk) {
            float a[TM], b[TN];
#pragma unroll
            for (int i = 0; i < TM; i++) a[i] = As[kk][rowBase + i];
#pragma unroll
            for (int j = 0; j < TN; j++) b[j] = Bs[kk][colBase + j];
#pragma unroll
            for (int i = 0; i < TM; i++)
#pragma unroll
                for (int j = 0; j < TN; j++) acc[i][j] = fmaf(a[i], b[j], acc[i][j]);
        }
        __syncthreads();
    }

    const float4 bv = *(const float4*)(bias + n0 + colBase);
#pragma unroll
    for (int i = 0; i < TM; i++) {
        int gr = m0 + rowBase + i;
        if (gr >= M) continue;
        float4 o;
        o.x = acc[i][0] + bv.x;
        o.y = acc[i][1] + bv.y;
        o.z = acc[i][2] + bv.z;
        o.w = acc[i][3] + bv.w;
        if (RELU) {
            o.x = fmaxf(o.x, 0.f); o.y = fmaxf(o.y, 0.f);
            o.z = fmaxf(o.z, 0.f); o.w = fmaxf(o.w, 0.f);
        }
        *(float4*)(C + (size_t)gr * Nout + n0 + colBase) = o;
    }
}

__global__ void gemm1_kernel(const float* __restrict__ A,
                             const float* __restrict__ B,
                             const float* __restrict__ bias)
{
    gemm_body<true>(A, B, bias, g_h, NN, DIN, DH);
}

__global__ void gemm2_kernel()
{
    gemm_body<false>(g_h, g_W2, g_b2, g_qkvs, NN, DH, 512);
}

// ---------------- pack 4 projection weights into one [512, 128] matrix --------
__global__ void pack_w_kernel(const float* __restrict__ wq, const float* __restrict__ bq,
                              const float* __restrict__ wk, const float* __restrict__ bk,
                              const float* __restrict__ wv, const float* __restrict__ bv,
                              const float* __restrict__ ws, const float* __restrict__ bs)
{
    int i = blockIdx.x * blockDim.x + threadIdx.x;
    if (i < 512 * DH) {
        int o = i / DH, k = i % DH;
        const float* w = (o < 128) ? wq : (o < 256) ? wk : (o < 384) ? wv : ws;
        g_W2[i] = w[(o & 127) * DH + k];
    }
    if (i < 512) {
        const float* b = (i < 128) ? bq : (i < 256) ? bk : (i < 384) ? bv : bs;
        g_b2[i] = b[i & 127];
    }
}

// ---------------- CSR build ----------------------------------------------------
__device__ __forceinline__ int load_edge(const int* ei_raw, int e, int half)
{
    // half = 0 -> src row, half = 1 -> dst row
    if (g_is64) {
        // int64 layout: [2, E] of 64-bit -> little-endian lo word at index 2*(half*EE+e)
        return ei_raw[2 * (half * EE + e)];
    } else {
        return ei_raw[half * EE + e];
    }
}

__global__ void zero_deg_kernel()
{
    int i = blockIdx.x * blockDim.x + threadIdx.x;
    if (i < NN) g_deg[i] = 0;
}

__global__ void count_deg_kernel(const int* __restrict__ ei_raw)
{
    int e = blockIdx.x * blockDim.x + threadIdx.x;
    if (e < EE) {
        int dst = load_edge(ei_raw, e, 1);
        if (dst >= 0 && dst < NN) atomicAdd(&g_deg[dst], 1);
    }
}

__global__ void scan_kernel()
{
    __shared__ int part[1024];
    const int t = threadIdx.x;
    const int CH = (NN + 1023) / 1024;
    const int st = t * CH;
    int s = 0;
    for (int i = 0; i < CH; i++) {
        int idx = st + i;
        if (idx < NN) s += g_deg[idx];
    }
    part[t] = s;
    __syncthreads();
    for (int o = 1; o < 1024; o <<= 1) {
        int v = (t >= o) ? part[t - o] : 0;
        __syncthreads();
        part[t] += v;
        __syncthreads();
    }
    int run = (t == 0) ? 0 : part[t - 1];
    for (int i = 0; i < CH; i++) {
        int idx = st + i;
        if (idx < NN) {
            g_off[idx] = run;
            g_cur[idx] = run;
            run += g_deg[idx];
        }
    }
    if (t == 1023) g_off[NN] = part[1023];
}

__global__ void scatter_kernel(const int* __restrict__ ei_raw)
{
    int e = blockIdx.x * blockDim.x + threadIdx.x;
    if (e < EE) {
        int src = load_edge(ei_raw, e, 0);
        int dst = load_edge(ei_raw, e, 1);
        if (src >= 0 && src < NN && dst >= 0 && dst < NN) {
            int pos = atomicAdd(&g_cur[dst], 1);
            if (pos >= 0 && pos < EE) g_src[pos] = src;
        }
    }
}

// ---------------- per-node online-softmax aggregation: one warp per node -------
__global__ void agg_kernel(float* __restrict__ out)
{
    int warp = (blockIdx.x * blockDim.x + threadIdx.x) >> 5;
    int lane = threadIdx.x & 31;
    if (warp >= NN) return;

    const float* myq = g_qkvs + (size_t)warp * 512;
    const float4 q = *(const float4*)(myq + 4 * lane);

    const int s = g_off[warp];
    const int e = g_off[warp + 1];

    const float scale = 0.088388347648318447f;  // 1/sqrt(128)
    float m = -INFINITY, l = 0.f;
    float4 acc = make_float4(0.f, 0.f, 0.f, 0.f);

    for (int j = s; j < e; j++) {
        int src = g_src[j];
        const float* base = g_qkvs + (size_t)src * 512;
        float4 kk = *(const float4*)(base + 128 + 4 * lane);
        float d = q.x * kk.x + q.y * kk.y + q.z * kk.z + q.w * kk.w;
        d += __shfl_xor_sync(0xffffffffu, d, 16);
        d += __shfl_xor_sync(0xffffffffu, d, 8);
        d += __shfl_xor_sync(0xffffffffu, d, 4);
        d += __shfl_xor_sync(0xffffffffu, d, 2);
        d += __shfl_xor_sync(0xffffffffu, d, 1);
        d *= scale;

        float newm = fmaxf(m, d);
        float fac = __expf(m - newm);   // m=-inf on first edge -> 0
        float p   = __expf(d - newm);
        l = l * fac + p;

        float4 vv = *(const float4*)(base + 256 + 4 * lane);
        acc.x = acc.x * fac + p * vv.x;
        acc.y = acc.y * fac + p * vv.y;
        acc.z = acc.z * fac + p * vv.z;
        acc.w = acc.w * fac + p * vv.w;
        m = newm;
    }

    const float4 sk = *(const float4*)(myq + 384 + 4 * lane);
    float inv = (e > s) ? (1.f / l) : 0.f;
    float4 o;
    o.x = acc.x * inv + sk.x;
    o.y = acc.y * inv + sk.y;
    o.z = acc.z * inv + sk.z;
    o.w = acc.w * inv + sk.w;
    *(float4*)(out + (size_t)warp * DOUT + 4 * lane) = o;
}

// ---------------- launch --------------------------------------------------------
extern "C" void kernel_launch(void* const* d_in, const int* in_sizes, int n_in,
                              void* d_out, int out_size)
{
    const float* x    = (const float*)d_in[0];
    const int*   ei   = (const int*)d_in[1];   // raw words; dtype detected on device
    const float* W_fc = (const float*)d_in[2];
    const float* b_fc = (const float*)d_in[3];
    const float* W_q  = (const float*)d_in[4];
    const float* b_q  = (const float*)d_in[5];
    const float* W_k  = (const float*)d_in[6];
    const float* b_k  = (const float*)d_in[7];
    const float* W_v  = (const float*)d_in[8];
    const float* b_v  = (const float*)d_in[9];
    const float* W_s  = (const float*)d_in[10];
    const float* b_s  = (const float*)d_in[11];
    float* out = (float*)d_out;

    // edge dtype detection (device-side, deterministic)
    detect_dtype_kernel<<<1, 256>>>(ei);

    // CSR build
    zero_deg_kernel<<<(NN + 255) / 256, 256>>>();
    count_deg_kernel<<<(EE + 255) / 256, 256>>>(ei);
    scan_kernel<<<1, 1024>>>();
    scatter_kernel<<<(EE + 255) / 256, 256>>>(ei);

    // weight packing
    pack_w_kernel<<<(512 * DH + 255) / 256, 256>>>(W_q, b_q, W_k, b_k, W_v, b_v, W_s, b_s);

    // GEMM1: h = relu(x @ W_fc^T + b_fc)   [50000,256] x [128,256]^T
    {
        dim3 grid((NN + 127) / 128, DH / 64);
        gemm1_kernel<<<grid, 256>>>(x, W_fc, b_fc);
    }
    // GEMM2: qkvs = h @ W2^T + b2          [50000,128] x [512,128]^T
    {
        dim3 grid((NN + 127) / 128, 512 / 64);
        gemm2_kernel<<<grid, 256>>>();
    }

    // per-node online softmax + aggregation + skip
    agg_kernel<<<(NN * 32 + 255) / 256, 256>>>(out);
}

// round 5
// speedup vs baseline: 1.5773x; 1.5773x over previous
#include <cuda_runtime.h>
#include <cuda_bf16.h>
#include <math.h>
#include <stdint.h>

#define NN 50000
#define EE 800000
#define DIN 256
#define DH 128
#define DOUT 128

// ---------------- scratch (device globals; no allocation allowed) -------------
__device__ __nv_bfloat16 g_x_hi[(size_t)NN * DIN];  // 25.6 MB
__device__ __nv_bfloat16 g_x_lo[(size_t)NN * DIN];
__device__ __nv_bfloat16 g_h_hi[(size_t)NN * DH];   // 12.8 MB
__device__ __nv_bfloat16 g_h_lo[(size_t)NN * DH];
__device__ __nv_bfloat16 g_w1_hi[DH * DIN];
__device__ __nv_bfloat16 g_w1_lo[DH * DIN];
__device__ __nv_bfloat16 g_w2_hi[512 * DH];
__device__ __nv_bfloat16 g_w2_lo[512 * DH];
__device__ float g_b2[512];
__device__ float g_qkvs[(size_t)NN * 512];          // 102.4 MB : per node [q k v skip]
__device__ int   g_deg[NN];
__device__ int   g_off[NN + 1];
__device__ int   g_cur[NN];
__device__ int   g_src[EE];
__device__ int   g_part[256];
__device__ int   g_is64;

// ---------------- helpers ------------------------------------------------------
__device__ __forceinline__ uint32_t pack_hi2(float a, float b) {
    __nv_bfloat162 t = __floats2bfloat162_rn(a, b);
    return *(uint32_t*)&t;
}
__device__ __forceinline__ uint32_t pack_lo2(float a, float b) {
    float ra = a - __bfloat162float(__float2bfloat16_rn(a));
    float rb = b - __bfloat162float(__float2bfloat16_rn(b));
    __nv_bfloat162 t = __floats2bfloat162_rn(ra, rb);
    return *(uint32_t*)&t;
}

__device__ __forceinline__ void mma_bf16(float d[4], const uint32_t a[4], const uint32_t b[2]) {
    asm volatile(
        "mma.sync.aligned.m16n8k16.row.col.f32.bf16.bf16.f32 "
        "{%0,%1,%2,%3}, {%4,%5,%6,%7}, {%8,%9}, {%0,%1,%2,%3};"
        : "+f"(d[0]), "+f"(d[1]), "+f"(d[2]), "+f"(d[3])
        : "r"(a[0]), "r"(a[1]), "r"(a[2]), "r"(a[3]), "r"(b[0]), "r"(b[1]));
}

// ---------------- conversion kernels -------------------------------------------
__global__ void conv_x_kernel(const float* __restrict__ x)
{
    int i = blockIdx.x * blockDim.x + threadIdx.x;       // pair index
    if (i < NN * DIN / 2) {
        float2 v = ((const float2*)x)[i];
        ((uint32_t*)g_x_hi)[i] = pack_hi2(v.x, v.y);
        ((uint32_t*)g_x_lo)[i] = pack_lo2(v.x, v.y);
    }
}

__global__ void conv_w1_kernel(const float* __restrict__ w)
{
    int i = blockIdx.x * blockDim.x + threadIdx.x;
    if (i < DH * DIN / 2) {
        float2 v = ((const float2*)w)[i];
        ((uint32_t*)g_w1_hi)[i] = pack_hi2(v.x, v.y);
        ((uint32_t*)g_w1_lo)[i] = pack_lo2(v.x, v.y);
    }
}

__global__ void conv_w2_kernel(const float* __restrict__ wq, const float* __restrict__ bq,
                               const float* __restrict__ wk, const float* __restrict__ bk,
                               const float* __restrict__ wv, const float* __restrict__ bv,
                               const float* __restrict__ ws, const float* __restrict__ bs)
{
    int i = blockIdx.x * blockDim.x + threadIdx.x;       // pair index over 512*128/2
    if (i < 512 * DH / 2) {
        int row = (2 * i) / DH;                          // 0..511
        int kp  = i % (DH / 2);                          // pair within row
        const float* w = (row < 128) ? wq : (row < 256) ? wk : (row < 384) ? wv : ws;
        const float2 v = ((const float2*)(w + (row & 127) * DH))[kp];
        ((uint32_t*)g_w2_hi)[i] = pack_hi2(v.x, v.y);
        ((uint32_t*)g_w2_lo)[i] = pack_lo2(v.x, v.y);
    }
    if (i < 512) {
        const float* b = (i < 128) ? bq : (i < 256) ? bk : (i < 384) ? bv : bs;
        g_b2[i] = b[i & 127];
    }
}

// ---------------- mma.sync bf16-split GEMM -------------------------------------
// C[m][n] = act(sum_k A[m][k]*B[n][k] + bias[n]); A,B pre-split bf16 hi/lo.
// CTA tile 128x64, 8 warps as 4(M) x 2(N), warp tile 32x32 = 2 m16 x 4 n8 mma tiles.
// G1: A=g_x (K=256), B=g_w1, out=relu -> g_h_hi/lo (bf16).
// !G1: A=g_h (K=128), B=g_w2, out -> g_qkvs (f32, ldc=512).
template<int K, bool G1>
__global__ __launch_bounds__(256, 2) void mma_gemm_kernel(const float* __restrict__ bias_in)
{
    constexpr int PAD = 40;   // bf16 pitch: 80B rows -> conflict-free frag LDS
    __shared__ __nv_bfloat16 Ash[128 * PAD], Asl[128 * PAD];
    __shared__ __nv_bfloat16 Bsh[64 * PAD],  Bsl[64 * PAD];

    const __nv_bfloat16* __restrict__ Ahi = G1 ? g_x_hi : g_h_hi;
    const __nv_bfloat16* __restrict__ Alo = G1 ? g_x_lo : g_h_lo;
    const __nv_bfloat16* __restrict__ Bhi = G1 ? g_w1_hi : g_w2_hi;
    const __nv_bfloat16* __restrict__ Blo = G1 ? g_w1_lo : g_w2_lo;
    const float* __restrict__ bias = G1 ? bias_in : g_b2;

    const int tid = threadIdx.x, lane = tid & 31, wid = tid >> 5;
    const int warpM = wid & 3, warpN = wid >> 2;
    const int m0 = blockIdx.x * 128, n0 = blockIdx.y * 64;

    float acc[2][4][4];
#pragma unroll
    for (int mt = 0; mt < 2; mt++)
#pragma unroll
        for (int nt = 0; nt < 4; nt++)
#pragma unroll
            for (int r = 0; r < 4; r++) acc[mt][nt][r] = 0.f;

    for (int k0 = 0; k0 < K; k0 += 32) {
        // fill A tiles: 128 rows x 32 bf16 = 512 16B-chunks (2 per thread, hi+lo)
#pragma unroll
        for (int it = 0; it < 2; it++) {
            int c = tid + it * 256;
            int row = c >> 2, quad = c & 3;
            int grow = m0 + row;
            uint4 vh = make_uint4(0, 0, 0, 0), vl = make_uint4(0, 0, 0, 0);
            if (grow < NN) {
                vh = *(const uint4*)(Ahi + (size_t)grow * K + k0 + quad * 8);
                vl = *(const uint4*)(Alo + (size_t)grow * K + k0 + quad * 8);
            }
            *(uint4*)(Ash + row * PAD + quad * 8) = vh;
            *(uint4*)(Asl + row * PAD + quad * 8) = vl;
        }
        // fill B tiles: 64 rows x 32 bf16 = 256 chunks (1 per thread, hi+lo)
        {
            int row = tid >> 2, quad = tid & 3;
            uint4 vh = *(const uint4*)(Bhi + (size_t)(n0 + row) * K + k0 + quad * 8);
            uint4 vl = *(const uint4*)(Blo + (size_t)(n0 + row) * K + k0 + quad * 8);
            *(uint4*)(Bsh + row * PAD + quad * 8) = vh;
            *(uint4*)(Bsl + row * PAD + quad * 8) = vl;
        }
        __syncthreads();

#pragma unroll
        for (int ks = 0; ks < 2; ks++) {
            const int kb = ks * 16 + 2 * (lane & 3);
            uint32_t ah[2][4], al[2][4], bh[4][2], bl[4][2];
#pragma unroll
            for (int mt = 0; mt < 2; mt++) {
                int r = warpM * 32 + mt * 16 + (lane >> 2);
                ah[mt][0] = *(const uint32_t*)(Ash + r * PAD + kb);
                ah[mt][1] = *(const uint32_t*)(Ash + (r + 8) * PAD + kb);
                ah[mt][2] = *(const uint32_t*)(Ash + r * PAD + kb + 8);
                ah[mt][3] = *(const uint32_t*)(Ash + (r + 8) * PAD + kb + 8);
                al[mt][0] = *(const uint32_t*)(Asl + r * PAD + kb);
                al[mt][1] = *(const uint32_t*)(Asl + (r + 8) * PAD + kb);
                al[mt][2] = *(const uint32_t*)(Asl + r * PAD + kb + 8);
                al[mt][3] = *(const uint32_t*)(Asl + (r + 8) * PAD + kb + 8);
            }
#pragma unroll
            for (int nt = 0; nt < 4; nt++) {
                int r = warpN * 32 + nt * 8 + (lane >> 2);
                bh[nt][0] = *(const uint32_t*)(Bsh + r * PAD + kb);
                bh[nt][1] = *(const uint32_t*)(Bsh + r * PAD + kb + 8);
                bl[nt][0] = *(const uint32_t*)(Bsl + r * PAD + kb);
                bl[nt][1] = *(const uint32_t*)(Bsl + r * PAD + kb + 8);
            }
#pragma unroll
            for (int mt = 0; mt < 2; mt++)
#pragma unroll
                for (int nt = 0; nt < 4; nt++) {
                    mma_bf16(acc[mt][nt], ah[mt], bh[nt]);
                    mma_bf16(acc[mt][nt], ah[mt], bl[nt]);
                    mma_bf16(acc[mt][nt], al[mt], bh[nt]);
                }
        }
        __syncthreads();
    }

    // epilogue
#pragma unroll
    for (int mt = 0; mt < 2; mt++) {
        int r0 = m0 + warpM * 32 + mt * 16 + (lane >> 2);
#pragma unroll
        for (int nt = 0; nt < 4; nt++) {
            int col = n0 + warpN * 32 + nt * 8 + 2 * (lane & 3);
            float b0 = bias[col], b1 = bias[col + 1];
            float v0 = acc[mt][nt][0] + b0, v1 = acc[mt][nt][1] + b1;
            float v2 = acc[mt][nt][2] + b0, v3 = acc[mt][nt][3] + b1;
            if (G1) {
                v0 = fmaxf(v0, 0.f); v1 = fmaxf(v1, 0.f);
                v2 = fmaxf(v2, 0.f); v3 = fmaxf(v3, 0.f);
                if (r0 < NN) {
                    *(uint32_t*)(g_h_hi + (size_t)r0 * DH + col) = pack_hi2(v0, v1);
                    *(uint32_t*)(g_h_lo + (size_t)r0 * DH + col) = pack_lo2(v0, v1);
                }
                if (r0 + 8 < NN) {
                    *(uint32_t*)(g_h_hi + (size_t)(r0 + 8) * DH + col) = pack_hi2(v2, v3);
                    *(uint32_t*)(g_h_lo + (size_t)(r0 + 8) * DH + col) = pack_lo2(v2, v3);
                }
            } else {
                if (r0 < NN) { float2 o = {v0, v1}; *(float2*)(g_qkvs + (size_t)r0 * 512 + col) = o; }
                if (r0 + 8 < NN) { float2 o = {v2, v3}; *(float2*)(g_qkvs + (size_t)(r0 + 8) * 512 + col) = o; }
            }
        }
    }
}

// ---------------- edge dtype detection ----------------------------------------
__global__ void detect_dtype_kernel(const int* __restrict__ ei_raw)
{
    __shared__ int nz;
    if (threadIdx.x == 0) nz = 0;
    __syncthreads();
    int w = ei_raw[2 * threadIdx.x + 1];
    if (w != 0) atomicAdd(&nz, 1);
    __syncthreads();
    if (threadIdx.x == 0) g_is64 = (nz == 0) ? 1 : 0;
}

// ---------------- CSR build ----------------------------------------------------
__device__ __forceinline__ int load_edge(const int* ei_raw, int e, int half)
{
    if (g_is64) return ei_raw[2 * (half * EE + e)];
    else        return ei_raw[half * EE + e];
}

__global__ void zero_deg_kernel()
{
    int i = blockIdx.x * blockDim.x + threadIdx.x;
    if (i < NN) g_deg[i] = 0;
}

__global__ void count_deg_kernel(const int* __restrict__ ei_raw)
{
    int e = blockIdx.x * blockDim.x + threadIdx.x;
    if (e < EE) {
        int dst = load_edge(ei_raw, e, 1);
        if (dst >= 0 && dst < NN) atomicAdd(&g_deg[dst], 1);
    }
}

#define SCAN_BLKS ((NN + 255) / 256)
__global__ void scan1_kernel()
{
    __shared__ int sm[256];
    int i = blockIdx.x * 256 + threadIdx.x;
    sm[threadIdx.x] = (i < NN) ? g_deg[i] : 0;
    __syncthreads();
    for (int o = 128; o > 0; o >>= 1) {
        if (threadIdx.x < o) sm[threadIdx.x] += sm[threadIdx.x + o];
        __syncthreads();
    }
    if (threadIdx.x == 0) g_part[blockIdx.x] = sm[0];
}

__global__ void scan2_kernel()
{
    __shared__ int sm[256];
    int t = threadIdx.x;
    int v = (t < SCAN_BLKS) ? g_part[t] : 0;
    sm[t] = v;
    __syncthreads();
    for (int o = 1; o < 256; o <<= 1) {
        int u = (t >= o) ? sm[t - o] : 0;
        __syncthreads();
        sm[t] += u;
        __syncthreads();
    }
    if (t < SCAN_BLKS) g_part[t] = sm[t] - v;   // exclusive
    if (t == 255) g_off[NN] = sm[255];
}

__global__ void scan3_kernel()
{
    __shared__ int sm[256];
    int i = blockIdx.x * 256 + threadIdx.x;
    int v = (i < NN) ? g_deg[i] : 0;
    sm[threadIdx.x] = v;
    __syncthreads();
    for (int o = 1; o < 256; o <<= 1) {
        int u = (threadIdx.x >= o) ? sm[threadIdx.x - o] : 0;
        __syncthreads();
        sm[threadIdx.x] += u;
        __syncthreads();
    }
    if (i < NN) {
        int off = g_part[blockIdx.x] + sm[threadIdx.x] - v;
        g_off[i] = off;
        g_cur[i] = off;
    }
}

__global__ void scatter_kernel(const int* __restrict__ ei_raw)
{
    int e = blockIdx.x * blockDim.x + threadIdx.x;
    if (e < EE) {
        int src = load_edge(ei_raw, e, 0);
        int dst = load_edge(ei_raw, e, 1);
        if (src >= 0 && src < NN && dst >= 0 && dst < NN) {
            int pos = atomicAdd(&g_cur[dst], 1);
            if (pos >= 0 && pos < EE) g_src[pos] = src;
        }
    }
}

// ---------------- per-node online-softmax aggregation: one warp per node -------
__global__ void agg_kernel(float* __restrict__ out)
{
    int warp = (blockIdx.x * blockDim.x + threadIdx.x) >> 5;
    int lane = threadIdx.x & 31;
    if (warp >= NN) return;

    const float* myq = g_qkvs + (size_t)warp * 512;
    const float4 q = *(const float4*)(myq + 4 * lane);

    const int s = g_off[warp];
    const int e = g_off[warp + 1];

    const float scale = 0.088388347648318447f;  // 1/sqrt(128)
    float m = -INFINITY, l = 0.f;
    float4 acc = make_float4(0.f, 0.f, 0.f, 0.f);

    for (int j = s; j < e; j++) {
        int src = g_src[j];
        const float* base = g_qkvs + (size_t)src * 512;
        float4 kk = *(const float4*)(base + 128 + 4 * lane);
        float d = q.x * kk.x + q.y * kk.y + q.z * kk.z + q.w * kk.w;
        d += __shfl_xor_sync(0xffffffffu, d, 16);
        d += __shfl_xor_sync(0xffffffffu, d, 8);
        d += __shfl_xor_sync(0xffffffffu, d, 4);
        d += __shfl_xor_sync(0xffffffffu, d, 2);
        d += __shfl_xor_sync(0xffffffffu, d, 1);
        d *= scale;

        float newm = fmaxf(m, d);
        float fac = __expf(m - newm);
        float p   = __expf(d - newm);
        l = l * fac + p;

        float4 vv = *(const float4*)(base + 256 + 4 * lane);
        acc.x = acc.x * fac + p * vv.x;
        acc.y = acc.y * fac + p * vv.y;
        acc.z = acc.z * fac + p * vv.z;
        acc.w = acc.w * fac + p * vv.w;
        m = newm;
    }

    const float4 sk = *(const float4*)(myq + 384 + 4 * lane);
    float inv = (e > s) ? (1.f / l) : 0.f;
    float4 o;
    o.x = acc.x * inv + sk.x;
    o.y = acc.y * inv + sk.y;
    o.z = acc.z * inv + sk.z;
    o.w = acc.w * inv + sk.w;
    *(float4*)(out + (size_t)warp * DOUT + 4 * lane) = o;
}

// ---------------- launch --------------------------------------------------------
extern "C" void kernel_launch(void* const* d_in, const int* in_sizes, int n_in,
                              void* d_out, int out_size)
{
    const float* x    = (const float*)d_in[0];
    const int*   ei   = (const int*)d_in[1];
    const float* W_fc = (const float*)d_in[2];
    const float* b_fc = (const float*)d_in[3];
    const float* W_q  = (const float*)d_in[4];
    const float* b_q  = (const float*)d_in[5];
    const float* W_k  = (const float*)d_in[6];
    const float* b_k  = (const float*)d_in[7];
    const float* W_v  = (const float*)d_in[8];
    const float* b_v  = (const float*)d_in[9];
    const float* W_s  = (const float*)d_in[10];
    const float* b_s  = (const float*)d_in[11];
    float* out = (float*)d_out;

    detect_dtype_kernel<<<1, 256>>>(ei);

    // CSR build
    zero_deg_kernel<<<(NN + 255) / 256, 256>>>();
    count_deg_kernel<<<(EE + 255) / 256, 256>>>(ei);
    scan1_kernel<<<SCAN_BLKS, 256>>>();
    scan2_kernel<<<1, 256>>>();
    scan3_kernel<<<SCAN_BLKS, 256>>>();
    scatter_kernel<<<(EE + 255) / 256, 256>>>(ei);

    // bf16 hi/lo conversions
    conv_x_kernel<<<(NN * DIN / 2 + 255) / 256, 256>>>(x);
    conv_w1_kernel<<<(DH * DIN / 2 + 255) / 256, 256>>>(W_fc);
    conv_w2_kernel<<<(512 * DH / 2 + 255) / 256, 256>>>(W_q, b_q, W_k, b_k, W_v, b_v, W_s, b_s);

    // GEMM1: h = relu(x @ W_fc^T + b_fc)   [50000,256] x [128,256]^T -> bf16 hi/lo
    {
        dim3 grid((NN + 127) / 128, DH / 64);
        mma_gemm_kernel<DIN, true><<<grid, 256>>>(b_fc);
    }
    // GEMM2: qkvs = h @ W2^T + b2          [50000,128] x [512,128]^T -> f32
    {
        dim3 grid((NN + 127) / 128, 512 / 64);
        mma_gemm_kernel<DH, false><<<grid, 256>>>(nullptr);
    }

    // per-node online softmax + aggregation + skip
    agg_kernel<<<(NN * 32 + 255) / 256, 256>>>(out);
}

// round 6
// speedup vs baseline: 2.0298x; 1.2869x over previous
#include <cuda_runtime.h>
#include <cuda_bf16.h>
#include <math.h>
#include <stdint.h>

#define NN 50000
#define EE 800000
#define DIN 256
#define DH 128
#define DOUT 128

// ---------------- scratch (device globals; no allocation allowed) -------------
__device__ __nv_bfloat16 g_h_hi[(size_t)NN * DH];   // 12.8 MB
__device__ __nv_bfloat16 g_h_lo[(size_t)NN * DH];
__device__ __nv_bfloat16 g_w2_hi[512 * DH];
__device__ __nv_bfloat16 g_w2_lo[512 * DH];
__device__ float g_b2[512];
__device__ float g_qkvs[(size_t)NN * 512];          // 102.4 MB : per node [q k v skip]
__device__ int   g_deg[NN];
__device__ int   g_off[NN + 1];
__device__ int   g_cur[NN];
__device__ int   g_src[EE];
__device__ int   g_part[256];
__device__ int   g_is64;

// ---------------- helpers ------------------------------------------------------
__device__ __forceinline__ uint32_t pack_hi2(float a, float b) {
    __nv_bfloat162 t = __floats2bfloat162_rn(a, b);
    return *(uint32_t*)&t;
}
__device__ __forceinline__ uint32_t pack_lo2(float a, float b) {
    float ra = a - __bfloat162float(__float2bfloat16_rn(a));
    float rb = b - __bfloat162float(__float2bfloat16_rn(b));
    __nv_bfloat162 t = __floats2bfloat162_rn(ra, rb);
    return *(uint32_t*)&t;
}

__device__ __forceinline__ void mma_bf16(float d[4], const uint32_t a[4], const uint32_t b[2]) {
    asm volatile(
        "mma.sync.aligned.m16n8k16.row.col.f32.bf16.bf16.f32 "
        "{%0,%1,%2,%3}, {%4,%5,%6,%7}, {%8,%9}, {%0,%1,%2,%3};"
        : "+f"(d[0]), "+f"(d[1]), "+f"(d[2]), "+f"(d[3])
        : "r"(a[0]), "r"(a[1]), "r"(a[2]), "r"(a[3]), "r"(b[0]), "r"(b[1]));
}

// ---------------- GEMM1: h = relu(x @ W_fc^T + b_fc) ---------------------------
// Fused fp32->bf16 hi/lo conversion in the SMEM fill. CTA: 128 rows x all 128 cols.
// 8 warps = 4(M) x 2(N); warp tile 32 x 64 = 2 m16 x 8 n8.
#define PAD1 40
__global__ __launch_bounds__(256) void g1_kernel(const float* __restrict__ x,
                                                 const float* __restrict__ w1,
                                                 const float* __restrict__ bias)
{
    __shared__ __nv_bfloat16 Ash[128 * PAD1], Asl[128 * PAD1];
    __shared__ __nv_bfloat16 Bsh[128 * PAD1], Bsl[128 * PAD1];

    const int tid = threadIdx.x, lane = tid & 31, wid = tid >> 5;
    const int warpM = wid & 3, warpN = wid >> 2;
    const int m0 = blockIdx.x * 128;

    float acc[2][8][4];
#pragma unroll
    for (int mt = 0; mt < 2; mt++)
#pragma unroll
        for (int nt = 0; nt < 8; nt++)
#pragma unroll
            for (int r = 0; r < 4; r++) acc[mt][nt][r] = 0.f;

    for (int k0 = 0; k0 < DIN; k0 += 32) {
        // A: 128 rows x 32 fp32 -> hi/lo bf16 (1024 float4 chunks)
#pragma unroll
        for (int it = 0; it < 4; it++) {
            int idx = tid + it * 256;
            int row = idx >> 3, c4 = idx & 7;
            int grow = m0 + row;
            float4 v = make_float4(0.f, 0.f, 0.f, 0.f);
            if (grow < NN) v = *(const float4*)(x + (size_t)grow * DIN + k0 + c4 * 4);
            uint2 h = make_uint2(pack_hi2(v.x, v.y), pack_hi2(v.z, v.w));
            uint2 l = make_uint2(pack_lo2(v.x, v.y), pack_lo2(v.z, v.w));
            *(uint2*)(Ash + row * PAD1 + c4 * 4) = h;
            *(uint2*)(Asl + row * PAD1 + c4 * 4) = l;
        }
        // B: W_fc 128 rows x 32 fp32 -> hi/lo
#pragma unroll
        for (int it = 0; it < 4; it++) {
            int idx = tid + it * 256;
            int row = idx >> 3, c4 = idx & 7;
            float4 v = *(const float4*)(w1 + (size_t)row * DIN + k0 + c4 * 4);
            uint2 h = make_uint2(pack_hi2(v.x, v.y), pack_hi2(v.z, v.w));
            uint2 l = make_uint2(pack_lo2(v.x, v.y), pack_lo2(v.z, v.w));
            *(uint2*)(Bsh + row * PAD1 + c4 * 4) = h;
            *(uint2*)(Bsl + row * PAD1 + c4 * 4) = l;
        }
        __syncthreads();

#pragma unroll
        for (int ks = 0; ks < 2; ks++) {
            const int kb = ks * 16 + 2 * (lane & 3);
            uint32_t ah[2][4], al[2][4];
#pragma unroll
            for (int mt = 0; mt < 2; mt++) {
                int r = warpM * 32 + mt * 16 + (lane >> 2);
                ah[mt][0] = *(const uint32_t*)(Ash + r * PAD1 + kb);
                ah[mt][1] = *(const uint32_t*)(Ash + (r + 8) * PAD1 + kb);
                ah[mt][2] = *(const uint32_t*)(Ash + r * PAD1 + kb + 8);
                ah[mt][3] = *(const uint32_t*)(Ash + (r + 8) * PAD1 + kb + 8);
                al[mt][0] = *(const uint32_t*)(Asl + r * PAD1 + kb);
                al[mt][1] = *(const uint32_t*)(Asl + (r + 8) * PAD1 + kb);
                al[mt][2] = *(const uint32_t*)(Asl + r * PAD1 + kb + 8);
                al[mt][3] = *(const uint32_t*)(Asl + (r + 8) * PAD1 + kb + 8);
            }
#pragma unroll
            for (int nt = 0; nt < 8; nt++) {
                int r = warpN * 64 + nt * 8 + (lane >> 2);
                uint32_t bh[2], bl[2];
                bh[0] = *(const uint32_t*)(Bsh + r * PAD1 + kb);
                bh[1] = *(const uint32_t*)(Bsh + r * PAD1 + kb + 8);
                bl[0] = *(const uint32_t*)(Bsl + r * PAD1 + kb);
                bl[1] = *(const uint32_t*)(Bsl + r * PAD1 + kb + 8);
#pragma unroll
                for (int mt = 0; mt < 2; mt++) {
                    mma_bf16(acc[mt][nt], ah[mt], bh);
                    mma_bf16(acc[mt][nt], ah[mt], bl);
                    mma_bf16(acc[mt][nt], al[mt], bh);
                }
            }
        }
        __syncthreads();
    }

    // epilogue: bias + relu -> g_h hi/lo (bf16)
#pragma unroll
    for (int mt = 0; mt < 2; mt++) {
        int r0 = m0 + warpM * 32 + mt * 16 + (lane >> 2);
#pragma unroll
        for (int nt = 0; nt < 8; nt++) {
            int col = warpN * 64 + nt * 8 + 2 * (lane & 3);
            float b0 = bias[col], b1 = bias[col + 1];
            float v0 = fmaxf(acc[mt][nt][0] + b0, 0.f);
            float v1 = fmaxf(acc[mt][nt][1] + b1, 0.f);
            float v2 = fmaxf(acc[mt][nt][2] + b0, 0.f);
            float v3 = fmaxf(acc[mt][nt][3] + b1, 0.f);
            if (r0 < NN) {
                *(uint32_t*)(g_h_hi + (size_t)r0 * DH + col) = pack_hi2(v0, v1);
                *(uint32_t*)(g_h_lo + (size_t)r0 * DH + col) = pack_lo2(v0, v1);
            }
            if (r0 + 8 < NN) {
                *(uint32_t*)(g_h_hi + (size_t)(r0 + 8) * DH + col) = pack_hi2(v2, v3);
                *(uint32_t*)(g_h_lo + (size_t)(r0 + 8) * DH + col) = pack_lo2(v2, v3);
            }
        }
    }
}

// ---------------- GEMM2: qkvs = h @ W2^T + b2 ----------------------------------
// A (h hi/lo, K=128) resident in SMEM for the whole CTA; loop 8 N-chunks of 64.
#define PA2 136
__global__ __launch_bounds__(256) void g2_kernel()
{
    extern __shared__ __nv_bfloat16 sm2[];
    __nv_bfloat16* Ash = sm2;                  // 128*136
    __nv_bfloat16* Asl = sm2 + 128 * PA2;
    __nv_bfloat16* Bsh = sm2 + 2 * 128 * PA2;  // 64*136
    __nv_bfloat16* Bsl = sm2 + 2 * 128 * PA2 + 64 * PA2;

    const int tid = threadIdx.x, lane = tid & 31, wid = tid >> 5;
    const int warpM = wid & 3, warpN = wid >> 2;
    const int m0 = blockIdx.x * 128;

    // load full A tile (128 x 128 hi/lo) once
#pragma unroll
    for (int it = 0; it < 8; it++) {
        int idx = tid + it * 256;                // 0..2047
        int row = idx >> 4, chunk = idx & 15;
        int grow = m0 + row;
        uint4 vh = make_uint4(0, 0, 0, 0), vl = make_uint4(0, 0, 0, 0);
        if (grow < NN) {
            vh = *(const uint4*)(g_h_hi + (size_t)grow * DH + chunk * 8);
            vl = *(const uint4*)(g_h_lo + (size_t)grow * DH + chunk * 8);
        }
        *(uint4*)(Ash + row * PA2 + chunk * 8) = vh;
        *(uint4*)(Asl + row * PA2 + chunk * 8) = vl;
    }
    __syncthreads();

    for (int nc = 0; nc < 8; nc++) {
        // load B chunk: rows nc*64..nc*64+63 of g_w2 (K=128)
#pragma unroll
        for (int it = 0; it < 4; it++) {
            int idx = tid + it * 256;            // 0..1023
            int row = idx >> 4, chunk = idx & 15;
            uint4 vh = *(const uint4*)(g_w2_hi + (size_t)(nc * 64 + row) * DH + chunk * 8);
            uint4 vl = *(const uint4*)(g_w2_lo + (size_t)(nc * 64 + row) * DH + chunk * 8);
            *(uint4*)(Bsh + row * PA2 + chunk * 8) = vh;
            *(uint4*)(Bsl + row * PA2 + chunk * 8) = vl;
        }
        __syncthreads();

        float acc[2][4][4];
#pragma unroll
        for (int mt = 0; mt < 2; mt++)
#pragma unroll
            for (int nt = 0; nt < 4; nt++)
#pragma unroll
                for (int r = 0; r < 4; r++) acc[mt][nt][r] = 0.f;

#pragma unroll
        for (int ks = 0; ks < 8; ks++) {
            const int kb = ks * 16 + 2 * (lane & 3);
            uint32_t ah[2][4], al[2][4];
#pragma unroll
            for (int mt = 0; mt < 2; mt++) {
                int r = warpM * 32 + mt * 16 + (lane >> 2);
                ah[mt][0] = *(const uint32_t*)(Ash + r * PA2 + kb);
                ah[mt][1] = *(const uint32_t*)(Ash + (r + 8) * PA2 + kb);
                ah[mt][2] = *(const uint32_t*)(Ash + r * PA2 + kb + 8);
                ah[mt][3] = *(const uint32_t*)(Ash + (r + 8) * PA2 + kb + 8);
                al[mt][0] = *(const uint32_t*)(Asl + r * PA2 + kb);
                al[mt][1] = *(const uint32_t*)(Asl + (r + 8) * PA2 + kb);
                al[mt][2] = *(const uint32_t*)(Asl + r * PA2 + kb + 8);
                al[mt][3] = *(const uint32_t*)(Asl + (r + 8) * PA2 + kb + 8);
            }
#pragma unroll
            for (int nt = 0; nt < 4; nt++) {
                int r = warpN * 32 + nt * 8 + (lane >> 2);
                uint32_t bh[2], bl[2];
                bh[0] = *(const uint32_t*)(Bsh + r * PA2 + kb);
                bh[1] = *(const uint32_t*)(Bsh + r * PA2 + kb + 8);
                bl[0] = *(const uint32_t*)(Bsl + r * PA2 + kb);
                bl[1] = *(const uint32_t*)(Bsl + r * PA2 + kb + 8);
#pragma unroll
                for (int mt = 0; mt < 2; mt++) {
                    mma_bf16(acc[mt][nt], ah[mt], bh);
                    mma_bf16(acc[mt][nt], ah[mt], bl);
                    mma_bf16(acc[mt][nt], al[mt], bh);
                }
            }
        }

        // epilogue for this N-chunk
#pragma unroll
        for (int mt = 0; mt < 2; mt++) {
            int r0 = m0 + warpM * 32 + mt * 16 + (lane >> 2);
#pragma unroll
            for (int nt = 0; nt < 4; nt++) {
                int col = nc * 64 + warpN * 32 + nt * 8 + 2 * (lane & 3);
                float b0 = g_b2[col], b1 = g_b2[col + 1];
                if (r0 < NN) {
                    float2 o = {acc[mt][nt][0] + b0, acc[mt][nt][1] + b1};
                    *(float2*)(g_qkvs + (size_t)r0 * 512 + col) = o;
                }
                if (r0 + 8 < NN) {
                    float2 o = {acc[mt][nt][2] + b0, acc[mt][nt][3] + b1};
                    *(float2*)(g_qkvs + (size_t)(r0 + 8) * 512 + col) = o;
                }
            }
        }
        __syncthreads();
    }
}

// ---------------- W2 pack + convert (fp32 -> bf16 hi/lo) -----------------------
__global__ void conv_w2_kernel(const float* __restrict__ wq, const float* __restrict__ bq,
                               const float* __restrict__ wk, const float* __restrict__ bk,
                               const float* __restrict__ wv, const float* __restrict__ bv,
                               const float* __restrict__ ws, const float* __restrict__ bs)
{
    int i = blockIdx.x * blockDim.x + threadIdx.x;       // pair index over 512*128/2
    if (i < 512 * DH / 2) {
        int row = (2 * i) / DH;
        int kp  = i % (DH / 2);
        const float* w = (row < 128) ? wq : (row < 256) ? wk : (row < 384) ? wv : ws;
        const float2 v = ((const float2*)(w + (row & 127) * DH))[kp];
        ((uint32_t*)g_w2_hi)[i] = pack_hi2(v.x, v.y);
        ((uint32_t*)g_w2_lo)[i] = pack_lo2(v.x, v.y);
    }
    if (i < 512) {
        const float* b = (i < 128) ? bq : (i < 256) ? bk : (i < 384) ? bv : bs;
        g_b2[i] = b[i & 127];
    }
}

// ---------------- edge dtype detection ----------------------------------------
__global__ void detect_dtype_kernel(const int* __restrict__ ei_raw)
{
    __shared__ int nz;
    if (threadIdx.x == 0) nz = 0;
    __syncthreads();
    int w = ei_raw[2 * threadIdx.x + 1];
    if (w != 0) atomicAdd(&nz, 1);
    __syncthreads();
    if (threadIdx.x == 0) g_is64 = (nz == 0) ? 1 : 0;
}

// ---------------- CSR build ----------------------------------------------------
__device__ __forceinline__ int load_edge(const int* ei_raw, int e, int half)
{
    if (g_is64) return ei_raw[2 * (half * EE + e)];
    else        return ei_raw[half * EE + e];
}

__global__ void zero_deg_kernel()
{
    int i = blockIdx.x * blockDim.x + threadIdx.x;
    if (i < NN) g_deg[i] = 0;
}

__global__ void count_deg_kernel(const int* __restrict__ ei_raw)
{
    int e = blockIdx.x * blockDim.x + threadIdx.x;
    if (e < EE) {
        int dst = load_edge(ei_raw, e, 1);
        if (dst >= 0 && dst < NN) atomicAdd(&g_deg[dst], 1);
    }
}

#define SCAN_BLKS ((NN + 255) / 256)
__global__ void scan1_kernel()
{
    __shared__ int sm[256];
    int i = blockIdx.x * 256 + threadIdx.x;
    sm[threadIdx.x] = (i < NN) ? g_deg[i] : 0;
    __syncthreads();
    for (int o = 128; o > 0; o >>= 1) {
        if (threadIdx.x < o) sm[threadIdx.x] += sm[threadIdx.x + o];
        __syncthreads();
    }
    if (threadIdx.x == 0) g_part[blockIdx.x] = sm[0];
}

__global__ void scan2_kernel()
{
    __shared__ int sm[256];
    int t = threadIdx.x;
    int v = (t < SCAN_BLKS) ? g_part[t] : 0;
    sm[t] = v;
    __syncthreads();
    for (int o = 1; o < 256; o <<= 1) {
        int u = (t >= o) ? sm[t - o] : 0;
        __syncthreads();
        sm[t] += u;
        __syncthreads();
    }
    if (t < SCAN_BLKS) g_part[t] = sm[t] - v;   // exclusive
    if (t == 255) g_off[NN] = sm[255];
}

__global__ void scan3_kernel()
{
    __shared__ int sm[256];
    int i = blockIdx.x * 256 + threadIdx.x;
    int v = (i < NN) ? g_deg[i] : 0;
    sm[threadIdx.x] = v;
    __syncthreads();
    for (int o = 1; o < 256; o <<= 1) {
        int u = (threadIdx.x >= o) ? sm[threadIdx.x - o] : 0;
        __syncthreads();
        sm[threadIdx.x] += u;
        __syncthreads();
    }
    if (i < NN) {
        int off = g_part[blockIdx.x] + sm[threadIdx.x] - v;
        g_off[i] = off;
        g_cur[i] = off;
    }
}

__global__ void scatter_kernel(const int* __restrict__ ei_raw)
{
    int e = blockIdx.x * blockDim.x + threadIdx.x;
    if (e < EE) {
        int src = load_edge(ei_raw, e, 0);
        int dst = load_edge(ei_raw, e, 1);
        if (src >= 0 && src < NN && dst >= 0 && dst < NN) {
            int pos = atomicAdd(&g_cur[dst], 1);
            if (pos >= 0 && pos < EE) g_src[pos] = src;
        }
    }
}

// ---------------- per-node online-softmax aggregation: one warp per node -------
__global__ void agg_kernel(float* __restrict__ out)
{
    int warp = (blockIdx.x * blockDim.x + threadIdx.x) >> 5;
    int lane = threadIdx.x & 31;
    if (warp >= NN) return;

    const float* myq = g_qkvs + (size_t)warp * 512;
    const float4 q = *(const float4*)(myq + 4 * lane);

    const int s = g_off[warp];
    const int e = g_off[warp + 1];

    const float scale = 0.088388347648318447f;  // 1/sqrt(128)
    float m = -INFINITY, l = 0.f;
    float4 acc = make_float4(0.f, 0.f, 0.f, 0.f);

    for (int j = s; j < e; j++) {
        int src = g_src[j];
        const float* base = g_qkvs + (size_t)src * 512;
        float4 kk = *(const float4*)(base + 128 + 4 * lane);
        float d = q.x * kk.x + q.y * kk.y + q.z * kk.z + q.w * kk.w;
        d += __shfl_xor_sync(0xffffffffu, d, 16);
        d += __shfl_xor_sync(0xffffffffu, d, 8);
        d += __shfl_xor_sync(0xffffffffu, d, 4);
        d += __shfl_xor_sync(0xffffffffu, d, 2);
        d += __shfl_xor_sync(0xffffffffu, d, 1);
        d *= scale;

        float newm = fmaxf(m, d);
        float fac = __expf(m - newm);
        float p   = __expf(d - newm);
        l = l * fac + p;

        float4 vv = *(const float4*)(base + 256 + 4 * lane);
        acc.x = acc.x * fac + p * vv.x;
        acc.y = acc.y * fac + p * vv.y;
        acc.z = acc.z * fac + p * vv.z;
        acc.w = acc.w * fac + p * vv.w;
        m = newm;
    }

    const float4 sk = *(const float4*)(myq + 384 + 4 * lane);
    float inv = (e > s) ? (1.f / l) : 0.f;
    float4 o;
    o.x = acc.x * inv + sk.x;
    o.y = acc.y * inv + sk.y;
    o.z = acc.z * inv + sk.z;
    o.w = acc.w * inv + sk.w;
    *(float4*)(out + (size_t)warp * DOUT + 4 * lane) = o;
}

// ---------------- launch --------------------------------------------------------
extern "C" void kernel_launch(void* const* d_in, const int* in_sizes, int n_in,
                              void* d_out, int out_size)
{
    const float* x    = (const float*)d_in[0];
    const int*   ei   = (const int*)d_in[1];
    const float* W_fc = (const float*)d_in[2];
    const float* b_fc = (const float*)d_in[3];
    const float* W_q  = (const float*)d_in[4];
    const float* b_q  = (const float*)d_in[5];
    const float* W_k  = (const float*)d_in[6];
    const float* b_k  = (const float*)d_in[7];
    const float* W_v  = (const float*)d_in[8];
    const float* b_v  = (const float*)d_in[9];
    const float* W_s  = (const float*)d_in[10];
    const float* b_s  = (const float*)d_in[11];
    float* out = (float*)d_out;

    // one-time infra (host-side; no device memory)
    static cudaStream_t s_side = nullptr;
    static cudaEvent_t ev_fork = nullptr, ev_join = nullptr;
    if (!s_side) {
        cudaStreamCreateWithFlags(&s_side, cudaStreamNonBlocking);
        cudaEventCreateWithFlags(&ev_fork, cudaEventDisableTiming);
        cudaEventCreateWithFlags(&ev_join, cudaEventDisableTiming);
        const int SM2 = (2 * 128 * PA2 + 2 * 64 * PA2) * 2;  // 104448 B
        cudaFuncSetAttribute(g2_kernel, cudaFuncAttributeMaxDynamicSharedMemorySize, SM2);
    }
    const int SM2 = (2 * 128 * PA2 + 2 * 64 * PA2) * 2;

    // dtype detection feeds the CSR chain
    detect_dtype_kernel<<<1, 256>>>(ei);
    cudaEventRecord(ev_fork, 0);
    cudaStreamWaitEvent(s_side, ev_fork, 0);

    // --- side stream: CSR build (independent of GEMMs) ---
    zero_deg_kernel<<<(NN + 255) / 256, 256, 0, s_side>>>();
    count_deg_kernel<<<(EE + 255) / 256, 256, 0, s_side>>>(ei);
    scan1_kernel<<<SCAN_BLKS, 256, 0, s_side>>>();
    scan2_kernel<<<1, 256, 0, s_side>>>();
    scan3_kernel<<<SCAN_BLKS, 256, 0, s_side>>>();
    scatter_kernel<<<(EE + 255) / 256, 256, 0, s_side>>>(ei);
    cudaEventRecord(ev_join, s_side);

    // --- main stream: weights conversion + GEMMs ---
    conv_w2_kernel<<<(512 * DH / 2 + 255) / 256, 256>>>(W_q, b_q, W_k, b_k, W_v, b_v, W_s, b_s);
    g1_kernel<<<(NN + 127) / 128, 256>>>(x, W_fc, b_fc);
    g2_kernel<<<(NN + 127) / 128, 256, SM2>>>();

    // join, then aggregate
    cudaStreamWaitEvent(0, ev_join, 0);
    agg_kernel<<<(NN * 32 + 255) / 256, 256>>>(out);
}

// round 7
// speedup vs baseline: 2.2613x; 1.1140x over previous
#include <cuda_runtime.h>
#include <cuda_bf16.h>
#include <math.h>
#include <stdint.h>

#define NN 50000
#define EE 800000
#define DIN 256
#define DH 128
#define DOUT 128

// ---------------- scratch (device globals; no allocation allowed) -------------
__device__ __nv_bfloat16 g_h_hi[(size_t)NN * DH];   // 12.8 MB
__device__ __nv_bfloat16 g_h_lo[(size_t)NN * DH];
__device__ __nv_bfloat16 g_w2_hi[512 * DH];
__device__ __nv_bfloat16 g_w2_lo[512 * DH];
__device__ float g_b2[512];
__device__ float g_qkvs[(size_t)NN * 512];          // 102.4 MB : per node [q k v skip]
__device__ int   g_deg[NN];
__device__ int   g_off[NN + 1];
__device__ int   g_cur[NN];
__device__ int   g_src[EE];
__device__ int   g_part[256];
__device__ int   g_is64;

// ---------------- helpers ------------------------------------------------------
__device__ __forceinline__ uint32_t pack_hi2(float a, float b) {
    __nv_bfloat162 t = __floats2bfloat162_rn(a, b);
    return *(uint32_t*)&t;
}
__device__ __forceinline__ uint32_t pack_lo2(float a, float b) {
    float ra = a - __bfloat162float(__float2bfloat16_rn(a));
    float rb = b - __bfloat162float(__float2bfloat16_rn(b));
    __nv_bfloat162 t = __floats2bfloat162_rn(ra, rb);
    return *(uint32_t*)&t;
}

__device__ __forceinline__ void mma_bf16(float d[4], const uint32_t a[4], const uint32_t b[2]) {
    asm volatile(
        "mma.sync.aligned.m16n8k16.row.col.f32.bf16.bf16.f32 "
        "{%0,%1,%2,%3}, {%4,%5,%6,%7}, {%8,%9}, {%0,%1,%2,%3};"
        : "+f"(d[0]), "+f"(d[1]), "+f"(d[2]), "+f"(d[3])
        : "r"(a[0]), "r"(a[1]), "r"(a[2]), "r"(a[3]), "r"(b[0]), "r"(b[1]));
}

// ---------------- GEMM1: h = relu(x @ W_fc^T + b_fc) ---------------------------
// Fused fp32->bf16 hi/lo conversion; double-buffered via register staging.
// CTA: 128 rows x 128 cols. 8 warps = 4(M) x 2(N); warp tile 32x64.
#define PAD1 40
__global__ __launch_bounds__(256) void g1_kernel(const float* __restrict__ x,
                                                 const float* __restrict__ w1,
                                                 const float* __restrict__ bias)
{
    __shared__ __nv_bfloat16 Ash[128 * PAD1], Asl[128 * PAD1];
    __shared__ __nv_bfloat16 Bsh[128 * PAD1], Bsl[128 * PAD1];

    const int tid = threadIdx.x, lane = tid & 31, wid = tid >> 5;
    const int warpM = wid & 3, warpN = wid >> 2;
    const int m0 = blockIdx.x * 128;

    float acc[2][8][4];
#pragma unroll
    for (int mt = 0; mt < 2; mt++)
#pragma unroll
        for (int nt = 0; nt < 8; nt++)
#pragma unroll
            for (int r = 0; r < 4; r++) acc[mt][nt][r] = 0.f;

    // staging registers (tile k0 -> tile k0+32 prefetch)
    float4 rA[4], rB[4];
    const int arow = tid >> 3, ac4 = tid & 7;          // per-thread A slot (x4 via it)
    // NOTE: each 'it' handles idx = tid + it*256 -> row = idx>>3, c4 = idx&7.
    // Since 256/8 = 32, row advances by 32 per it and c4 repeats.
#pragma unroll
    for (int it = 0; it < 4; it++) {
        int row = arow + it * 32;
        int grow = m0 + row;
        rA[it] = (grow < NN) ? *(const float4*)(x + (size_t)grow * DIN + ac4 * 4)
                             : make_float4(0.f, 0.f, 0.f, 0.f);
        rB[it] = *(const float4*)(w1 + (size_t)row * DIN + ac4 * 4);
    }

    for (int k0 = 0; k0 < DIN; k0 += 32) {
        // store staged tile to SMEM with conversion
#pragma unroll
        for (int it = 0; it < 4; it++) {
            int row = arow + it * 32;
            float4 v = rA[it];
            *(uint2*)(Ash + row * PAD1 + ac4 * 4) = make_uint2(pack_hi2(v.x, v.y), pack_hi2(v.z, v.w));
            *(uint2*)(Asl + row * PAD1 + ac4 * 4) = make_uint2(pack_lo2(v.x, v.y), pack_lo2(v.z, v.w));
            v = rB[it];
            *(uint2*)(Bsh + row * PAD1 + ac4 * 4) = make_uint2(pack_hi2(v.x, v.y), pack_hi2(v.z, v.w));
            *(uint2*)(Bsl + row * PAD1 + ac4 * 4) = make_uint2(pack_lo2(v.x, v.y), pack_lo2(v.z, v.w));
        }
        __syncthreads();

        // prefetch next tile (overlaps with MMA below)
        if (k0 + 32 < DIN) {
#pragma unroll
            for (int it = 0; it < 4; it++) {
                int row = arow + it * 32;
                int grow = m0 + row;
                rA[it] = (grow < NN) ? *(const float4*)(x + (size_t)grow * DIN + k0 + 32 + ac4 * 4)
                                     : make_float4(0.f, 0.f, 0.f, 0.f);
                rB[it] = *(const float4*)(w1 + (size_t)row * DIN + k0 + 32 + ac4 * 4);
            }
        }

#pragma unroll
        for (int ks = 0; ks < 2; ks++) {
            const int kb = ks * 16 + 2 * (lane & 3);
            uint32_t ah[2][4], al[2][4];
#pragma unroll
            for (int mt = 0; mt < 2; mt++) {
                int r = warpM * 32 + mt * 16 + (lane >> 2);
                ah[mt][0] = *(const uint32_t*)(Ash + r * PAD1 + kb);
                ah[mt][1] = *(const uint32_t*)(Ash + (r + 8) * PAD1 + kb);
                ah[mt][2] = *(const uint32_t*)(Ash + r * PAD1 + kb + 8);
                ah[mt][3] = *(const uint32_t*)(Ash + (r + 8) * PAD1 + kb + 8);
                al[mt][0] = *(const uint32_t*)(Asl + r * PAD1 + kb);
                al[mt][1] = *(const uint32_t*)(Asl + (r + 8) * PAD1 + kb);
                al[mt][2] = *(const uint32_t*)(Asl + r * PAD1 + kb + 8);
                al[mt][3] = *(const uint32_t*)(Asl + (r + 8) * PAD1 + kb + 8);
            }
#pragma unroll
            for (int nt = 0; nt < 8; nt++) {
                int r = warpN * 64 + nt * 8 + (lane >> 2);
                uint32_t bh[2], bl[2];
                bh[0] = *(const uint32_t*)(Bsh + r * PAD1 + kb);
                bh[1] = *(const uint32_t*)(Bsh + r * PAD1 + kb + 8);
                bl[0] = *(const uint32_t*)(Bsl + r * PAD1 + kb);
                bl[1] = *(const uint32_t*)(Bsl + r * PAD1 + kb + 8);
#pragma unroll
                for (int mt = 0; mt < 2; mt++) {
                    mma_bf16(acc[mt][nt], ah[mt], bh);
                    mma_bf16(acc[mt][nt], ah[mt], bl);
                    mma_bf16(acc[mt][nt], al[mt], bh);
                }
            }
        }
        __syncthreads();
    }

    // epilogue: bias + relu -> g_h hi/lo (bf16)
#pragma unroll
    for (int mt = 0; mt < 2; mt++) {
        int r0 = m0 + warpM * 32 + mt * 16 + (lane >> 2);
#pragma unroll
        for (int nt = 0; nt < 8; nt++) {
            int col = warpN * 64 + nt * 8 + 2 * (lane & 3);
            float b0 = bias[col], b1 = bias[col + 1];
            float v0 = fmaxf(acc[mt][nt][0] + b0, 0.f);
            float v1 = fmaxf(acc[mt][nt][1] + b1, 0.f);
            float v2 = fmaxf(acc[mt][nt][2] + b0, 0.f);
            float v3 = fmaxf(acc[mt][nt][3] + b1, 0.f);
            if (r0 < NN) {
                *(uint32_t*)(g_h_hi + (size_t)r0 * DH + col) = pack_hi2(v0, v1);
                *(uint32_t*)(g_h_lo + (size_t)r0 * DH + col) = pack_lo2(v0, v1);
            }
            if (r0 + 8 < NN) {
                *(uint32_t*)(g_h_hi + (size_t)(r0 + 8) * DH + col) = pack_hi2(v2, v3);
                *(uint32_t*)(g_h_lo + (size_t)(r0 + 8) * DH + col) = pack_lo2(v2, v3);
            }
        }
    }
}

// ---------------- GEMM2: qkvs = h @ W2^T + b2 ----------------------------------
// A (h hi/lo, K=128) resident in SMEM; 8 N-chunks of 64 with B register staging.
#define PA2 136
__global__ __launch_bounds__(256) void g2_kernel()
{
    extern __shared__ __nv_bfloat16 sm2[];
    __nv_bfloat16* Ash = sm2;                  // 128*136
    __nv_bfloat16* Asl = sm2 + 128 * PA2;
    __nv_bfloat16* Bsh = sm2 + 2 * 128 * PA2;  // 64*136
    __nv_bfloat16* Bsl = sm2 + 2 * 128 * PA2 + 64 * PA2;

    const int tid = threadIdx.x, lane = tid & 31, wid = tid >> 5;
    const int warpM = wid & 3, warpN = wid >> 2;
    const int m0 = blockIdx.x * 128;
    const int brow = tid >> 4, bchunk = tid & 15;   // B slot (x4 via it, row += 16)

    // load full A tile (128 x 128 hi/lo) once
#pragma unroll
    for (int it = 0; it < 8; it++) {
        int idx = tid + it * 256;
        int row = idx >> 4, chunk = idx & 15;
        int grow = m0 + row;
        uint4 vh = make_uint4(0, 0, 0, 0), vl = make_uint4(0, 0, 0, 0);
        if (grow < NN) {
            vh = *(const uint4*)(g_h_hi + (size_t)grow * DH + chunk * 8);
            vl = *(const uint4*)(g_h_lo + (size_t)grow * DH + chunk * 8);
        }
        *(uint4*)(Ash + row * PA2 + chunk * 8) = vh;
        *(uint4*)(Asl + row * PA2 + chunk * 8) = vl;
    }

    // stage B chunk 0
    uint4 rBh[4], rBl[4];
#pragma unroll
    for (int it = 0; it < 4; it++) {
        int row = brow + it * 16;
        rBh[it] = *(const uint4*)(g_w2_hi + (size_t)row * DH + bchunk * 8);
        rBl[it] = *(const uint4*)(g_w2_lo + (size_t)row * DH + bchunk * 8);
    }
    __syncthreads();

    for (int nc = 0; nc < 8; nc++) {
        // store staged B chunk
#pragma unroll
        for (int it = 0; it < 4; it++) {
            int row = brow + it * 16;
            *(uint4*)(Bsh + row * PA2 + bchunk * 8) = rBh[it];
            *(uint4*)(Bsl + row * PA2 + bchunk * 8) = rBl[it];
        }
        __syncthreads();

        // prefetch next B chunk (overlaps MMA)
        if (nc + 1 < 8) {
#pragma unroll
            for (int it = 0; it < 4; it++) {
                int row = (nc + 1) * 64 + brow + it * 16;
                rBh[it] = *(const uint4*)(g_w2_hi + (size_t)row * DH + bchunk * 8);
                rBl[it] = *(const uint4*)(g_w2_lo + (size_t)row * DH + bchunk * 8);
            }
        }

        float acc[2][4][4];
#pragma unroll
        for (int mt = 0; mt < 2; mt++)
#pragma unroll
            for (int nt = 0; nt < 4; nt++)
#pragma unroll
                for (int r = 0; r < 4; r++) acc[mt][nt][r] = 0.f;

#pragma unroll
        for (int ks = 0; ks < 8; ks++) {
            const int kb = ks * 16 + 2 * (lane & 3);
            uint32_t ah[2][4], al[2][4];
#pragma unroll
            for (int mt = 0; mt < 2; mt++) {
                int r = warpM * 32 + mt * 16 + (lane >> 2);
                ah[mt][0] = *(const uint32_t*)(Ash + r * PA2 + kb);
                ah[mt][1] = *(const uint32_t*)(Ash + (r + 8) * PA2 + kb);
                ah[mt][2] = *(const uint32_t*)(Ash + r * PA2 + kb + 8);
                ah[mt][3] = *(const uint32_t*)(Ash + (r + 8) * PA2 + kb + 8);
                al[mt][0] = *(const uint32_t*)(Asl + r * PA2 + kb);
                al[mt][1] = *(const uint32_t*)(Asl + (r + 8) * PA2 + kb);
                al[mt][2] = *(const uint32_t*)(Asl + r * PA2 + kb + 8);
                al[mt][3] = *(const uint32_t*)(Asl + (r + 8) * PA2 + kb + 8);
            }
#pragma unroll
            for (int nt = 0; nt < 4; nt++) {
                int r = warpN * 32 + nt * 8 + (lane >> 2);
                uint32_t bh[2], bl[2];
                bh[0] = *(const uint32_t*)(Bsh + r * PA2 + kb);
                bh[1] = *(const uint32_t*)(Bsh + r * PA2 + kb + 8);
                bl[0] = *(const uint32_t*)(Bsl + r * PA2 + kb);
                bl[1] = *(const uint32_t*)(Bsl + r * PA2 + kb + 8);
#pragma unroll
                for (int mt = 0; mt < 2; mt++) {
                    mma_bf16(acc[mt][nt], ah[mt], bh);
                    mma_bf16(acc[mt][nt], ah[mt], bl);
                    mma_bf16(acc[mt][nt], al[mt], bh);
                }
            }
        }

        // epilogue for this N-chunk
#pragma unroll
        for (int mt = 0; mt < 2; mt++) {
            int r0 = m0 + warpM * 32 + mt * 16 + (lane >> 2);
#pragma unroll
            for (int nt = 0; nt < 4; nt++) {
                int col = nc * 64 + warpN * 32 + nt * 8 + 2 * (lane & 3);
                float b0 = g_b2[col], b1 = g_b2[col + 1];
                if (r0 < NN) {
                    float2 o = {acc[mt][nt][0] + b0, acc[mt][nt][1] + b1};
                    *(float2*)(g_qkvs + (size_t)r0 * 512 + col) = o;
                }
                if (r0 + 8 < NN) {
                    float2 o = {acc[mt][nt][2] + b0, acc[mt][nt][3] + b1};
                    *(float2*)(g_qkvs + (size_t)(r0 + 8) * 512 + col) = o;
                }
            }
        }
        __syncthreads();
    }
}

// ---------------- W2 pack + convert (fp32 -> bf16 hi/lo) -----------------------
__global__ void conv_w2_kernel(const float* __restrict__ wq, const float* __restrict__ bq,
                               const float* __restrict__ wk, const float* __restrict__ bk,
                               const float* __restrict__ wv, const float* __restrict__ bv,
                               const float* __restrict__ ws, const float* __restrict__ bs)
{
    int i = blockIdx.x * blockDim.x + threadIdx.x;
    if (i < 512 * DH / 2) {
        int row = (2 * i) / DH;
        int kp  = i % (DH / 2);
        const float* w = (row < 128) ? wq : (row < 256) ? wk : (row < 384) ? wv : ws;
        const float2 v = ((const float2*)(w + (row & 127) * DH))[kp];
        ((uint32_t*)g_w2_hi)[i] = pack_hi2(v.x, v.y);
        ((uint32_t*)g_w2_lo)[i] = pack_lo2(v.x, v.y);
    }
    if (i < 512) {
        const float* b = (i < 128) ? bq : (i < 256) ? bk : (i < 384) ? bv : bs;
        g_b2[i] = b[i & 127];
    }
}

// ---------------- edge dtype detection ----------------------------------------
__global__ void detect_dtype_kernel(const int* __restrict__ ei_raw)
{
    __shared__ int nz;
    if (threadIdx.x == 0) nz = 0;
    __syncthreads();
    int w = ei_raw[2 * threadIdx.x + 1];
    if (w != 0) atomicAdd(&nz, 1);
    __syncthreads();
    if (threadIdx.x == 0) g_is64 = (nz == 0) ? 1 : 0;
}

// ---------------- CSR build ----------------------------------------------------
__device__ __forceinline__ int load_edge(const int* ei_raw, int e, int half)
{
    if (g_is64) return ei_raw[2 * (half * EE + e)];
    else        return ei_raw[half * EE + e];
}

__global__ void zero_deg_kernel()
{
    int i = blockIdx.x * blockDim.x + threadIdx.x;
    if (i < NN) g_deg[i] = 0;
}

__global__ void count_deg_kernel(const int* __restrict__ ei_raw)
{
    int e = blockIdx.x * blockDim.x + threadIdx.x;
    if (e < EE) {
        int dst = load_edge(ei_raw, e, 1);
        if (dst >= 0 && dst < NN) atomicAdd(&g_deg[dst], 1);
    }
}

#define SCAN_BLKS ((NN + 255) / 256)
__global__ void scan1_kernel()
{
    __shared__ int sm[256];
    int i = blockIdx.x * 256 + threadIdx.x;
    sm[threadIdx.x] = (i < NN) ? g_deg[i] : 0;
    __syncthreads();
    for (int o = 128; o > 0; o >>= 1) {
        if (threadIdx.x < o) sm[threadIdx.x] += sm[threadIdx.x + o];
        __syncthreads();
    }
    if (threadIdx.x == 0) g_part[blockIdx.x] = sm[0];
}

__global__ void scan2_kernel()
{
    __shared__ int sm[256];
    int t = threadIdx.x;
    int v = (t < SCAN_BLKS) ? g_part[t] : 0;
    sm[t] = v;
    __syncthreads();
    for (int o = 1; o < 256; o <<= 1) {
        int u = (t >= o) ? sm[t - o] : 0;
        __syncthreads();
        sm[t] += u;
        __syncthreads();
    }
    if (t < SCAN_BLKS) g_part[t] = sm[t] - v;
    if (t == 255) g_off[NN] = sm[255];
}

__global__ void scan3_kernel()
{
    __shared__ int sm[256];
    int i = blockIdx.x * 256 + threadIdx.x;
    int v = (i < NN) ? g_deg[i] : 0;
    sm[threadIdx.x] = v;
    __syncthreads();
    for (int o = 1; o < 256; o <<= 1) {
        int u = (threadIdx.x >= o) ? sm[threadIdx.x - o] : 0;
        __syncthreads();
        sm[threadIdx.x] += u;
        __syncthreads();
    }
    if (i < NN) {
        int off = g_part[blockIdx.x] + sm[threadIdx.x] - v;
        g_off[i] = off;
        g_cur[i] = off;
    }
}

__global__ void scatter_kernel(const int* __restrict__ ei_raw)
{
    int e = blockIdx.x * blockDim.x + threadIdx.x;
    if (e < EE) {
        int src = load_edge(ei_raw, e, 0);
        int dst = load_edge(ei_raw, e, 1);
        if (src >= 0 && src < NN && dst >= 0 && dst < NN) {
            int pos = atomicAdd(&g_cur[dst], 1);
            if (pos >= 0 && pos < EE) g_src[pos] = src;
        }
    }
}

// ---------------- per-node online-softmax aggregation: one warp per node -------
// Software-pipelined: k/v loads for edge j+1 issue before edge j is consumed.
__global__ void agg_kernel(float* __restrict__ out)
{
    int warp = (blockIdx.x * blockDim.x + threadIdx.x) >> 5;
    int lane = threadIdx.x & 31;
    if (warp >= NN) return;

    const float* myq = g_qkvs + (size_t)warp * 512;
    const float4 q = *(const float4*)(myq + 4 * lane);

    const int s = g_off[warp];
    const int e = g_off[warp + 1];

    const float scale = 0.088388347648318447f;  // 1/sqrt(128)
    float m = -INFINITY, l = 0.f;
    float4 acc = make_float4(0.f, 0.f, 0.f, 0.f);

    if (e > s) {
        int src = g_src[s];
        const float* base = g_qkvs + (size_t)src * 512;
        float4 kk = *(const float4*)(base + 128 + 4 * lane);
        float4 vv = *(const float4*)(base + 256 + 4 * lane);

        for (int j = s; j < e; j++) {
            float4 kk_n, vv_n;
            if (j + 1 < e) {
                int src_n = g_src[j + 1];
                const float* base_n = g_qkvs + (size_t)src_n * 512;
                kk_n = *(const float4*)(base_n + 128 + 4 * lane);
                vv_n = *(const float4*)(base_n + 256 + 4 * lane);
            }

            float d = q.x * kk.x + q.y * kk.y + q.z * kk.z + q.w * kk.w;
            d += __shfl_xor_sync(0xffffffffu, d, 16);
            d += __shfl_xor_sync(0xffffffffu, d, 8);
            d += __shfl_xor_sync(0xffffffffu, d, 4);
            d += __shfl_xor_sync(0xffffffffu, d, 2);
            d += __shfl_xor_sync(0xffffffffu, d, 1);
            d *= scale;

            float newm = fmaxf(m, d);
            float fac = __expf(m - newm);
            float p   = __expf(d - newm);
            l = l * fac + p;

            acc.x = acc.x * fac + p * vv.x;
            acc.y = acc.y * fac + p * vv.y;
            acc.z = acc.z * fac + p * vv.z;
            acc.w = acc.w * fac + p * vv.w;
            m = newm;

            kk = kk_n;
            vv = vv_n;
        }
    }

    const float4 sk = *(const float4*)(myq + 384 + 4 * lane);
    float inv = (e > s) ? (1.f / l) : 0.f;
    float4 o;
    o.x = acc.x * inv + sk.x;
    o.y = acc.y * inv + sk.y;
    o.z = acc.z * inv + sk.z;
    o.w = acc.w * inv + sk.w;
    *(float4*)(out + (size_t)warp * DOUT + 4 * lane) = o;
}

// ---------------- launch --------------------------------------------------------
extern "C" void kernel_launch(void* const* d_in, const int* in_sizes, int n_in,
                              void* d_out, int out_size)
{
    const float* x    = (const float*)d_in[0];
    const int*   ei   = (const int*)d_in[1];
    const float* W_fc = (const float*)d_in[2];
    const float* b_fc = (const float*)d_in[3];
    const float* W_q  = (const float*)d_in[4];
    const float* b_q  = (const float*)d_in[5];
    const float* W_k  = (const float*)d_in[6];
    const float* b_k  = (const float*)d_in[7];
    const float* W_v  = (const float*)d_in[8];
    const float* b_v  = (const float*)d_in[9];
    const float* W_s  = (const float*)d_in[10];
    const float* b_s  = (const float*)d_in[11];
    float* out = (float*)d_out;

    // one-time infra (host-side; no device memory)
    static cudaStream_t s_side = nullptr;
    static cudaEvent_t ev_fork = nullptr, ev_join = nullptr;
    if (!s_side) {
        cudaStreamCreateWithFlags(&s_side, cudaStreamNonBlocking);
        cudaEventCreateWithFlags(&ev_fork, cudaEventDisableTiming);
        cudaEventCreateWithFlags(&ev_join, cudaEventDisableTiming);
        const int SM2 = (2 * 128 * PA2 + 2 * 64 * PA2) * 2;  // 104448 B
        cudaFuncSetAttribute(g2_kernel, cudaFuncAttributeMaxDynamicSharedMemorySize, SM2);
    }
    const int SM2 = (2 * 128 * PA2 + 2 * 64 * PA2) * 2;

    // dtype detection feeds the CSR chain
    detect_dtype_kernel<<<1, 256>>>(ei);
    cudaEventRecord(ev_fork, 0);
    cudaStreamWaitEvent(s_side, ev_fork, 0);

    // --- side stream: CSR build (independent of GEMMs) ---
    zero_deg_kernel<<<(NN + 255) / 256, 256, 0, s_side>>>();
    count_deg_kernel<<<(EE + 255) / 256, 256, 0, s_side>>>(ei);
    scan1_kernel<<<SCAN_BLKS, 256, 0, s_side>>>();
    scan2_kernel<<<1, 256, 0, s_side>>>();
    scan3_kernel<<<SCAN_BLKS, 256, 0, s_side>>>();
    scatter_kernel<<<(EE + 255) / 256, 256, 0, s_side>>>(ei);
    cudaEventRecord(ev_join, s_side);

    // --- main stream: weights conversion + GEMMs ---
    conv_w2_kernel<<<(512 * DH / 2 + 255) / 256, 256>>>(W_q, b_q, W_k, b_k, W_v, b_v, W_s, b_s);
    g1_kernel<<<(NN + 127) / 128, 256>>>(x, W_fc, b_fc);
    g2_kernel<<<(NN + 127) / 128, 256, SM2>>>();

    // join, then aggregate
    cudaStreamWaitEvent(0, ev_join, 0);
    agg_kernel<<<(NN * 32 + 255) / 256, 256>>>(out);
}

// round 8
// speedup vs baseline: 2.4441x; 1.0809x over previous
#include <cuda_runtime.h>
#include <cuda_bf16.h>
#include <math.h>
#include <stdint.h>

#define NN 50000
#define EE 800000
#define DIN 256
#define DH 128
#define DOUT 128

// ---------------- scratch (device globals; no allocation allowed) -------------
__device__ __nv_bfloat16 g_w2_hi[512 * DH];
__device__ __nv_bfloat16 g_w2_lo[512 * DH];
__device__ float g_b2[512];
__device__ float g_qkvs[(size_t)NN * 512];          // 102.4 MB : per node [q k v skip]
__device__ int   g_deg[NN];
__device__ int   g_off[NN + 1];
__device__ int   g_cur[NN];
__device__ int   g_src[EE];
__device__ int   g_part[256];
__device__ int   g_is64;

// ---------------- helpers ------------------------------------------------------
__device__ __forceinline__ uint32_t smem_u32(const void* p) {
    uint32_t a;
    asm("{ .reg .u64 t; cvta.to.shared.u64 t, %1; cvt.u32.u64 %0, t; }" : "=r"(a) : "l"(p));
    return a;
}
__device__ __forceinline__ uint32_t pack_hi2(float a, float b) {
    __nv_bfloat162 t = __floats2bfloat162_rn(a, b);
    return *(uint32_t*)&t;
}
__device__ __forceinline__ uint32_t pack_lo2(float a, float b) {
    float ra = a - __bfloat162float(__float2bfloat16_rn(a));
    float rb = b - __bfloat162float(__float2bfloat16_rn(b));
    __nv_bfloat162 t = __floats2bfloat162_rn(ra, rb);
    return *(uint32_t*)&t;
}
__device__ __forceinline__ void mma_bf16(float d[4], const uint32_t a[4], const uint32_t b[2]) {
    asm volatile(
        "mma.sync.aligned.m16n8k16.row.col.f32.bf16.bf16.f32 "
        "{%0,%1,%2,%3}, {%4,%5,%6,%7}, {%8,%9}, {%0,%1,%2,%3};"
        : "+f"(d[0]), "+f"(d[1]), "+f"(d[2]), "+f"(d[3])
        : "r"(a[0]), "r"(a[1]), "r"(a[2]), "r"(a[3]), "r"(b[0]), "r"(b[1]));
}
__device__ __forceinline__ void ldsm4(uint32_t r[4], uint32_t addr) {
    asm volatile("ldmatrix.sync.aligned.m8n8.x4.shared.b16 {%0,%1,%2,%3}, [%4];"
                 : "=r"(r[0]), "=r"(r[1]), "=r"(r[2]), "=r"(r[3]) : "r"(addr));
}

// ---------------- fused GEMM: x -> h (SMEM) -> qkvs -----------------------------
// Phase 1: h = relu(x @ W_fc^T + b_fc), 128 rows/CTA, h kept in SMEM (bf16 hi/lo).
// Phase 2: qkvs = h @ W2^T + b2, 8 N-chunks of 64, W2 streamed via aliased buffers.
#define PAD1 40    // x/w1 tile pitch (bf16 elems); 80B rows -> conflict-free LDSM
#define PH   136   // h / W2 pitch; 272B rows -> conflict-free LDSM
// SMEM element offsets (bf16)
#define OFF_ASH 0
#define OFF_ASL 5120
#define OFF_BSH 10240
#define OFF_BSL 15360
#define OFF_HH  20480
#define OFF_HL  37888
#define OFF_W2H 0
#define OFF_W2L 8704
#define SMEM_ELEMS 55296   // 110592 bytes

__global__ __launch_bounds__(256) void fused_kernel(const float* __restrict__ x,
                                                    const float* __restrict__ w1,
                                                    const float* __restrict__ bias1)
{
    extern __shared__ __nv_bfloat16 sm[];
    const int tid = threadIdx.x, lane = tid & 31, wid = tid >> 5;
    const int warpM = wid & 3, warpN = wid >> 2;
    const int m0 = blockIdx.x * 128;
    const uint32_t sb = smem_u32(sm);

    // per-lane ldmatrix selectors
    const int aRowSel = lane & 15;
    const int aColSel = (lane >> 4) << 3;
    const int bRowSel = ((lane >> 4) << 3) + (lane & 7);
    const int bColSel = ((lane >> 3) & 1) << 3;

    // ---------------- phase 1: K=256 mainloop -----------------------------------
    float acc[2][8][4];
#pragma unroll
    for (int mt = 0; mt < 2; mt++)
#pragma unroll
        for (int nt = 0; nt < 8; nt++)
#pragma unroll
            for (int r = 0; r < 4; r++) acc[mt][nt][r] = 0.f;

    float4 rA[4], rB[4];
    const int arow = tid >> 3, ac4 = tid & 7;
#pragma unroll
    for (int it = 0; it < 4; it++) {
        int row = arow + it * 32;
        int grow = m0 + row;
        rA[it] = (grow < NN) ? *(const float4*)(x + (size_t)grow * DIN + ac4 * 4)
                             : make_float4(0.f, 0.f, 0.f, 0.f);
        rB[it] = *(const float4*)(w1 + (size_t)row * DIN + ac4 * 4);
    }

    for (int k0 = 0; k0 < DIN; k0 += 32) {
#pragma unroll
        for (int it = 0; it < 4; it++) {
            int row = arow + it * 32;
            float4 v = rA[it];
            *(uint2*)(sm + OFF_ASH + row * PAD1 + ac4 * 4) = make_uint2(pack_hi2(v.x, v.y), pack_hi2(v.z, v.w));
            *(uint2*)(sm + OFF_ASL + row * PAD1 + ac4 * 4) = make_uint2(pack_lo2(v.x, v.y), pack_lo2(v.z, v.w));
            v = rB[it];
            *(uint2*)(sm + OFF_BSH + row * PAD1 + ac4 * 4) = make_uint2(pack_hi2(v.x, v.y), pack_hi2(v.z, v.w));
            *(uint2*)(sm + OFF_BSL + row * PAD1 + ac4 * 4) = make_uint2(pack_lo2(v.x, v.y), pack_lo2(v.z, v.w));
        }
        __syncthreads();

        if (k0 + 32 < DIN) {
#pragma unroll
            for (int it = 0; it < 4; it++) {
                int row = arow + it * 32;
                int grow = m0 + row;
                rA[it] = (grow < NN) ? *(const float4*)(x + (size_t)grow * DIN + k0 + 32 + ac4 * 4)
                                     : make_float4(0.f, 0.f, 0.f, 0.f);
                rB[it] = *(const float4*)(w1 + (size_t)row * DIN + k0 + 32 + ac4 * 4);
            }
        }

#pragma unroll
        for (int ks = 0; ks < 2; ks++) {
            const int kb = ks * 16;
            uint32_t ah[2][4], al[2][4];
#pragma unroll
            for (int mt = 0; mt < 2; mt++) {
                uint32_t a_addr = sb + 2 * (OFF_ASH + (warpM * 32 + mt * 16 + aRowSel) * PAD1 + kb + aColSel);
                ldsm4(ah[mt], a_addr);
                ldsm4(al[mt], a_addr + 2 * (OFF_ASL - OFF_ASH));
            }
#pragma unroll
            for (int p = 0; p < 4; p++) {
                uint32_t b_addr = sb + 2 * (OFF_BSH + (warpN * 64 + p * 16 + bRowSel) * PAD1 + kb + bColSel);
                uint32_t bh[4], bl[4];
                ldsm4(bh, b_addr);
                ldsm4(bl, b_addr + 2 * (OFF_BSL - OFF_BSH));
#pragma unroll
                for (int mt = 0; mt < 2; mt++) {
                    mma_bf16(acc[mt][2 * p],     ah[mt], bh);
                    mma_bf16(acc[mt][2 * p],     ah[mt], bl);
                    mma_bf16(acc[mt][2 * p],     al[mt], bh);
                    mma_bf16(acc[mt][2 * p + 1], ah[mt], bh + 2);
                    mma_bf16(acc[mt][2 * p + 1], ah[mt], bl + 2);
                    mma_bf16(acc[mt][2 * p + 1], al[mt], bh + 2);
                }
            }
        }
        __syncthreads();
    }

    // prefetch W2 chunk 0 (overlaps h epilogue)
    uint4 rWh[4], rWl[4];
    const int brow = tid >> 4, bchunk = tid & 15;
#pragma unroll
    for (int it = 0; it < 4; it++) {
        int row = brow + it * 16;
        rWh[it] = *(const uint4*)(g_w2_hi + (size_t)row * DH + bchunk * 8);
        rWl[it] = *(const uint4*)(g_w2_lo + (size_t)row * DH + bchunk * 8);
    }

    // h epilogue: bias + relu -> SMEM (bf16 hi/lo)
#pragma unroll
    for (int mt = 0; mt < 2; mt++) {
        int r0 = warpM * 32 + mt * 16 + (lane >> 2);
#pragma unroll
        for (int nt = 0; nt < 8; nt++) {
            int col = warpN * 64 + nt * 8 + 2 * (lane & 3);
            float b0 = bias1[col], b1 = bias1[col + 1];
            float v0 = fmaxf(acc[mt][nt][0] + b0, 0.f);
            float v1 = fmaxf(acc[mt][nt][1] + b1, 0.f);
            float v2 = fmaxf(acc[mt][nt][2] + b0, 0.f);
            float v3 = fmaxf(acc[mt][nt][3] + b1, 0.f);
            *(uint32_t*)(sm + OFF_HH + r0 * PH + col) = pack_hi2(v0, v1);
            *(uint32_t*)(sm + OFF_HL + r0 * PH + col) = pack_lo2(v0, v1);
            *(uint32_t*)(sm + OFF_HH + (r0 + 8) * PH + col) = pack_hi2(v2, v3);
            *(uint32_t*)(sm + OFF_HL + (r0 + 8) * PH + col) = pack_lo2(v2, v3);
        }
    }
    __syncthreads();

    // ---------------- phase 2: qkvs = h @ W2^T + b2 ------------------------------
    for (int nc = 0; nc < 8; nc++) {
        // store staged W2 chunk into aliased buffers
#pragma unroll
        for (int it = 0; it < 4; it++) {
            int row = brow + it * 16;
            *(uint4*)(sm + OFF_W2H + row * PH + bchunk * 8) = rWh[it];
            *(uint4*)(sm + OFF_W2L + row * PH + bchunk * 8) = rWl[it];
        }
        __syncthreads();

        if (nc + 1 < 8) {
#pragma unroll
            for (int it = 0; it < 4; it++) {
                int row = (nc + 1) * 64 + brow + it * 16;
                rWh[it] = *(const uint4*)(g_w2_hi + (size_t)row * DH + bchunk * 8);
                rWl[it] = *(const uint4*)(g_w2_lo + (size_t)row * DH + bchunk * 8);
            }
        }

        float a2[2][4][4];
#pragma unroll
        for (int mt = 0; mt < 2; mt++)
#pragma unroll
            for (int nt = 0; nt < 4; nt++)
#pragma unroll
                for (int r = 0; r < 4; r++) a2[mt][nt][r] = 0.f;

#pragma unroll
        for (int ks = 0; ks < 8; ks++) {
            const int kb = ks * 16;
            uint32_t ah[2][4], al[2][4];
#pragma unroll
            for (int mt = 0; mt < 2; mt++) {
                uint32_t a_addr = sb + 2 * (OFF_HH + (warpM * 32 + mt * 16 + aRowSel) * PH + kb + aColSel);
                ldsm4(ah[mt], a_addr);
                ldsm4(al[mt], a_addr + 2 * (OFF_HL - OFF_HH));
            }
#pragma unroll
            for (int p = 0; p < 2; p++) {
                uint32_t b_addr = sb + 2 * (OFF_W2H + (warpN * 32 + p * 16 + bRowSel) * PH + kb + bColSel);
                uint32_t bh[4], bl[4];
                ldsm4(bh, b_addr);
                ldsm4(bl, b_addr + 2 * (OFF_W2L - OFF_W2H));
#pragma unroll
                for (int mt = 0; mt < 2; mt++) {
                    mma_bf16(a2[mt][2 * p],     ah[mt], bh);
                    mma_bf16(a2[mt][2 * p],     ah[mt], bl);
                    mma_bf16(a2[mt][2 * p],     al[mt], bh);
                    mma_bf16(a2[mt][2 * p + 1], ah[mt], bh + 2);
                    mma_bf16(a2[mt][2 * p + 1], ah[mt], bl + 2);
                    mma_bf16(a2[mt][2 * p + 1], al[mt], bh + 2);
                }
            }
        }

        // epilogue for this N-chunk -> g_qkvs
#pragma unroll
        for (int mt = 0; mt < 2; mt++) {
            int r0 = m0 + warpM * 32 + mt * 16 + (lane >> 2);
#pragma unroll
            for (int nt = 0; nt < 4; nt++) {
                int col = nc * 64 + warpN * 32 + nt * 8 + 2 * (lane & 3);
                float b0 = g_b2[col], b1 = g_b2[col + 1];
                if (r0 < NN) {
                    float2 o = {a2[mt][nt][0] + b0, a2[mt][nt][1] + b1};
                    *(float2*)(g_qkvs + (size_t)r0 * 512 + col) = o;
                }
                if (r0 + 8 < NN) {
                    float2 o = {a2[mt][nt][2] + b0, a2[mt][nt][3] + b1};
                    *(float2*)(g_qkvs + (size_t)(r0 + 8) * 512 + col) = o;
                }
            }
        }
        __syncthreads();
    }
}

// ---------------- W2 pack + convert (fp32 -> bf16 hi/lo) -----------------------
__global__ void conv_w2_kernel(const float* __restrict__ wq, const float* __restrict__ bq,
                               const float* __restrict__ wk, const float* __restrict__ bk,
                               const float* __restrict__ wv, const float* __restrict__ bv,
                               const float* __restrict__ ws, const float* __restrict__ bs)
{
    int i = blockIdx.x * blockDim.x + threadIdx.x;
    if (i < 512 * DH / 2) {
        int row = (2 * i) / DH;
        int kp  = i % (DH / 2);
        const float* w = (row < 128) ? wq : (row < 256) ? wk : (row < 384) ? wv : ws;
        const float2 v = ((const float2*)(w + (row & 127) * DH))[kp];
        ((uint32_t*)g_w2_hi)[i] = pack_hi2(v.x, v.y);
        ((uint32_t*)g_w2_lo)[i] = pack_lo2(v.x, v.y);
    }
    if (i < 512) {
        const float* b = (i < 128) ? bq : (i < 256) ? bk : (i < 384) ? bv : bs;
        g_b2[i] = b[i & 127];
    }
}

// ---------------- edge dtype detection ----------------------------------------
__global__ void detect_dtype_kernel(const int* __restrict__ ei_raw)
{
    __shared__ int nz;
    if (threadIdx.x == 0) nz = 0;
    __syncthreads();
    int w = ei_raw[2 * threadIdx.x + 1];
    if (w != 0) atomicAdd(&nz, 1);
    __syncthreads();
    if (threadIdx.x == 0) g_is64 = (nz == 0) ? 1 : 0;
}

// ---------------- CSR build ----------------------------------------------------
__device__ __forceinline__ int load_edge(const int* ei_raw, int e, int half)
{
    if (g_is64) return ei_raw[2 * (half * EE + e)];
    else        return ei_raw[half * EE + e];
}

__global__ void zero_deg_kernel()
{
    int i = blockIdx.x * blockDim.x + threadIdx.x;
    if (i < NN) g_deg[i] = 0;
}

__global__ void count_deg_kernel(const int* __restrict__ ei_raw)
{
    int e = blockIdx.x * blockDim.x + threadIdx.x;
    if (e < EE) {
        int dst = load_edge(ei_raw, e, 1);
        if (dst >= 0 && dst < NN) atomicAdd(&g_deg[dst], 1);
    }
}

#define SCAN_BLKS ((NN + 255) / 256)
__global__ void scan1_kernel()
{
    __shared__ int sm[256];
    int i = blockIdx.x * 256 + threadIdx.x;
    sm[threadIdx.x] = (i < NN) ? g_deg[i] : 0;
    __syncthreads();
    for (int o = 128; o > 0; o >>= 1) {
        if (threadIdx.x < o) sm[threadIdx.x] += sm[threadIdx.x + o];
        __syncthreads();
    }
    if (threadIdx.x == 0) g_part[blockIdx.x] = sm[0];
}

__global__ void scan2_kernel()
{
    __shared__ int sm[256];
    int t = threadIdx.x;
    int v = (t < SCAN_BLKS) ? g_part[t] : 0;
    sm[t] = v;
    __syncthreads();
    for (int o = 1; o < 256; o <<= 1) {
        int u = (t >= o) ? sm[t - o] : 0;
        __syncthreads();
        sm[t] += u;
        __syncthreads();
    }
    if (t < SCAN_BLKS) g_part[t] = sm[t] - v;
    if (t == 255) g_off[NN] = sm[255];
}

__global__ void scan3_kernel()
{
    __shared__ int sm[256];
    int i = blockIdx.x * 256 + threadIdx.x;
    int v = (i < NN) ? g_deg[i] : 0;
    sm[threadIdx.x] = v;
    __syncthreads();
    for (int o = 1; o < 256; o <<= 1) {
        int u = (threadIdx.x >= o) ? sm[threadIdx.x - o] : 0;
        __syncthreads();
        sm[threadIdx.x] += u;
        __syncthreads();
    }
    if (i < NN) {
        int off = g_part[blockIdx.x] + sm[threadIdx.x] - v;
        g_off[i] = off;
        g_cur[i] = off;
    }
}

__global__ void scatter_kernel(const int* __restrict__ ei_raw)
{
    int e = blockIdx.x * blockDim.x + threadIdx.x;
    if (e < EE) {
        int src = load_edge(ei_raw, e, 0);
        int dst = load_edge(ei_raw, e, 1);
        if (src >= 0 && src < NN && dst >= 0 && dst < NN) {
            int pos = atomicAdd(&g_cur[dst], 1);
            if (pos >= 0 && pos < EE) g_src[pos] = src;
        }
    }
}

// ---------------- per-node online-softmax aggregation: one warp per node -------
__global__ void agg_kernel(float* __restrict__ out)
{
    int warp = (blockIdx.x * blockDim.x + threadIdx.x) >> 5;
    int lane = threadIdx.x & 31;
    if (warp >= NN) return;

    const float* myq = g_qkvs + (size_t)warp * 512;
    const float4 q = *(const float4*)(myq + 4 * lane);

    const int s = g_off[warp];
    const int e = g_off[warp + 1];

    const float scale = 0.088388347648318447f;  // 1/sqrt(128)
    float m = -INFINITY, l = 0.f;
    float4 acc = make_float4(0.f, 0.f, 0.f, 0.f);

    if (e > s) {
        int src = g_src[s];
        const float* base = g_qkvs + (size_t)src * 512;
        float4 kk = *(const float4*)(base + 128 + 4 * lane);
        float4 vv = *(const float4*)(base + 256 + 4 * lane);

        for (int j = s; j < e; j++) {
            float4 kk_n, vv_n;
            if (j + 1 < e) {
                int src_n = g_src[j + 1];
                const float* base_n = g_qkvs + (size_t)src_n * 512;
                kk_n = *(const float4*)(base_n + 128 + 4 * lane);
                vv_n = *(const float4*)(base_n + 256 + 4 * lane);
            }

            float d = q.x * kk.x + q.y * kk.y + q.z * kk.z + q.w * kk.w;
            d += __shfl_xor_sync(0xffffffffu, d, 16);
            d += __shfl_xor_sync(0xffffffffu, d, 8);
            d += __shfl_xor_sync(0xffffffffu, d, 4);
            d += __shfl_xor_sync(0xffffffffu, d, 2);
            d += __shfl_xor_sync(0xffffffffu, d, 1);
            d *= scale;

            float newm = fmaxf(m, d);
            float fac = __expf(m - newm);
            float p   = __expf(d - newm);
            l = l * fac + p;

            acc.x = acc.x * fac + p * vv.x;
            acc.y = acc.y * fac + p * vv.y;
            acc.z = acc.z * fac + p * vv.z;
            acc.w = acc.w * fac + p * vv.w;
            m = newm;

            kk = kk_n;
            vv = vv_n;
        }
    }

    const float4 sk = *(const float4*)(myq + 384 + 4 * lane);
    float inv = (e > s) ? (1.f / l) : 0.f;
    float4 o;
    o.x = acc.x * inv + sk.x;
    o.y = acc.y * inv + sk.y;
    o.z = acc.z * inv + sk.z;
    o.w = acc.w * inv + sk.w;
    *(float4*)(out + (size_t)warp * DOUT + 4 * lane) = o;
}

// ---------------- launch --------------------------------------------------------
extern "C" void kernel_launch(void* const* d_in, const int* in_sizes, int n_in,
                              void* d_out, int out_size)
{
    const float* x    = (const float*)d_in[0];
    const int*   ei   = (const int*)d_in[1];
    const float* W_fc = (const float*)d_in[2];
    const float* b_fc = (const float*)d_in[3];
    const float* W_q  = (const float*)d_in[4];
    const float* b_q  = (const float*)d_in[5];
    const float* W_k  = (const float*)d_in[6];
    const float* b_k  = (const float*)d_in[7];
    const float* W_v  = (const float*)d_in[8];
    const float* b_v  = (const float*)d_in[9];
    const float* W_s  = (const float*)d_in[10];
    const float* b_s  = (const float*)d_in[11];
    float* out = (float*)d_out;

    static cudaStream_t s_side = nullptr;
    static cudaEvent_t ev_fork = nullptr, ev_join = nullptr;
    if (!s_side) {
        cudaStreamCreateWithFlags(&s_side, cudaStreamNonBlocking);
        cudaEventCreateWithFlags(&ev_fork, cudaEventDisableTiming);
        cudaEventCreateWithFlags(&ev_join, cudaEventDisableTiming);
        cudaFuncSetAttribute(fused_kernel, cudaFuncAttributeMaxDynamicSharedMemorySize,
                             SMEM_ELEMS * 2);
    }

    detect_dtype_kernel<<<1, 256>>>(ei);
    cudaEventRecord(ev_fork, 0);
    cudaStreamWaitEvent(s_side, ev_fork, 0);

    // --- side stream: CSR build (independent of GEMMs) ---
    zero_deg_kernel<<<(NN + 255) / 256, 256, 0, s_side>>>();
    count_deg_kernel<<<(EE + 255) / 256, 256, 0, s_side>>>(ei);
    scan1_kernel<<<SCAN_BLKS, 256, 0, s_side>>>();
    scan2_kernel<<<1, 256, 0, s_side>>>();
    scan3_kernel<<<SCAN_BLKS, 256, 0, s_side>>>();
    scatter_kernel<<<(EE + 255) / 256, 256, 0, s_side>>>(ei);
    cudaEventRecord(ev_join, s_side);

    // --- main stream: W2 conversion + fused GEMM ---
    conv_w2_kernel<<<(512 * DH / 2 + 255) / 256, 256>>>(W_q, b_q, W_k, b_k, W_v, b_v, W_s, b_s);
    fused_kernel<<<(NN + 127) / 128, 256, SMEM_ELEMS * 2>>>(x, W_fc, b_fc);

    // join, then aggregate
    cudaStreamWaitEvent(0, ev_join, 0);
    agg_kernel<<<(NN * 32 + 255) / 256, 256>>>(out);
}